// round 13
// baseline (speedup 1.0000x reference)
#include <cuda_runtime.h>
#include <cuda_bf16.h>
#include <math.h>
#include <stdint.h>

#define NROWS 8192
#define F     512
#define NCLS  8
#define ELLW  192

// ---------------- static scratch (device globals; no runtime alloc) ----------
__device__ __align__(16) float g_XW[NROWS * F];
__device__ __align__(16) float g_h [NROWS * F];
__device__ __align__(16) float g_R [NROWS * F];
__device__ __align__(16) float g_V [NROWS * F];
__device__ __align__(16) float g_Xt[NROWS * F];
__device__ __align__(16) float g_Y [NROWS * NCLS];
__device__ __align__(16) float g_N [F * F];
__device__ __align__(16) float g_u [F];
__device__ __align__(16) float g_v [F];
__device__ float g_c;
__device__ float g_bv[NROWS];
__device__ int   g_col[NROWS * ELLW];
__device__ int   g_len[NROWS];
__device__ float g_w  [NROWS * ELLW];
__device__ float g_w0 [NROWS];
__device__ __align__(16) float g_csum[F];
__device__ float g_part[32 * F];
// bf16 3-way splits
__device__ __align__(16) __nv_bfloat16 g_xs [3ull * NROWS * F];
__device__ __align__(16) __nv_bfloat16 g_hs [3ull * NROWS * F];
__device__ __align__(16) __nv_bfloat16 g_g1t[3 * F * F];
__device__ __align__(16) __nv_bfloat16 g_vwt[3 * F * F];
__device__ __align__(16) __nv_bfloat16 g_nts[3 * F * F];

// ---------------- helpers ----------------------------------------------------
__device__ __forceinline__ uint32_t smem_u32(const void* p) {
    uint32_t a;
    asm("{ .reg .u64 t; cvta.to.shared.u64 t, %1; cvt.u32.u64 %0, t; }" : "=r"(a) : "l"(p));
    return a;
}
template <int N> __device__ __forceinline__ void cp_wait() {
    asm volatile("cp.async.wait_group %0;" :: "n"(N));
}
__device__ __forceinline__ void cp_async16(uint32_t dst, const void* src) {
    asm volatile("cp.async.ca.shared.global [%0], [%1], 16;" :: "r"(dst), "l"(src));
}
__device__ __forceinline__ void cp_commit() {
    asm volatile("cp.async.commit_group;");
}
__device__ __forceinline__ void ldm_x4(uint32_t addr, uint32_t& r0, uint32_t& r1,
                                       uint32_t& r2, uint32_t& r3) {
    asm volatile("ldmatrix.sync.aligned.m8n8.x4.shared.b16 {%0,%1,%2,%3}, [%4];"
                 : "=r"(r0), "=r"(r1), "=r"(r2), "=r"(r3) : "r"(addr));
}
__device__ __forceinline__ void mma16816(float* c, const uint32_t* a, const uint32_t* b) {
    asm volatile(
        "mma.sync.aligned.m16n8k16.row.col.f32.bf16.bf16.f32 "
        "{%0,%1,%2,%3}, {%4,%5,%6,%7}, {%8,%9}, {%0,%1,%2,%3};"
        : "+f"(c[0]), "+f"(c[1]), "+f"(c[2]), "+f"(c[3])
        : "r"(a[0]), "r"(a[1]), "r"(a[2]), "r"(a[3]), "r"(b[0]), "r"(b[1]));
}

// ---------------- bf16 3-way split -------------------------------------------
__device__ __forceinline__ void split3(float x, __nv_bfloat16& b1, __nv_bfloat16& b2,
                                       __nv_bfloat16& b3) {
    b1 = __float2bfloat16(x);
    float r = x - __bfloat162float(b1);
    b2 = __float2bfloat16(r);
    float r2 = r - __bfloat162float(b2);
    b3 = __float2bfloat16(r2);
}

__global__ __launch_bounds__(256) void split_plain(const float* __restrict__ X,
                                                   __nv_bfloat16* __restrict__ out,
                                                   int nelem) {
    int i = (blockIdx.x * 256 + threadIdx.x) * 4;
    if (i >= nelem) return;
    float4 v = *(const float4*)(X + i);
    __nv_bfloat16 a[3][4];
    split3(v.x, a[0][0], a[1][0], a[2][0]);
    split3(v.y, a[0][1], a[1][1], a[2][1]);
    split3(v.z, a[0][2], a[1][2], a[2][2]);
    split3(v.w, a[0][3], a[1][3], a[2][3]);
#pragma unroll
    for (int s = 0; s < 3; s++)
        *(uint2*)(out + (size_t)s * nelem + i) = *(uint2*)a[s];
}

// W [F][F] fp32 -> out[s][n][k] = split_s(W[k][n])
__global__ void split_wt(const float* __restrict__ W, __nv_bfloat16* __restrict__ out) {
    __shared__ float t[32][33];
    int n0 = blockIdx.x * 32, k0 = blockIdx.y * 32;
    int tx = threadIdx.x, ty = threadIdx.y;
    t[ty][tx] = W[(size_t)(k0 + ty) * F + n0 + tx];
    __syncthreads();
    float x = t[tx][ty];
    __nv_bfloat16 b1, b2, b3;
    split3(x, b1, b2, b3);
    size_t o = (size_t)(n0 + ty) * F + k0 + tx;
    out[o] = b1;
    out[(size_t)F * F + o] = b2;
    out[2ull * F * F + o] = b3;
}

// ---------------- split-bf16 HMMA GEMM: C[M,512] = A@W (+bias) ---------------
// 3-stage cp.async pipeline, one barrier per chunk, 2 CTAs/SM.
#define NCH 96
__global__ __launch_bounds__(256, 2) void mma_gemm(const __nv_bfloat16* __restrict__ A3,
                                                   const __nv_bfloat16* __restrict__ B3,
                                                   const float* __restrict__ bias,
                                                   float* __restrict__ C) {
    __shared__ __align__(128) char sA[3][128 * 64];
    __shared__ __align__(128) char sB[3][128 * 64];
    const int tid = threadIdx.x, wid = tid >> 5, lane = tid & 31;
    const int n0 = blockIdx.x * 128, m0 = blockIdx.y * 128;
    const int wm = wid & 1, wn = wid >> 1;
    const size_t AS = (size_t)NROWS * F, BS = (size_t)F * F;
    const int pa[6] = {0, 0, 1, 0, 2, 1};
    const int pb[6] = {0, 1, 0, 2, 0, 1};

    uint32_t sAu[3] = {smem_u32(sA[0]), smem_u32(sA[1]), smem_u32(sA[2])};
    uint32_t sBu[3] = {smem_u32(sB[0]), smem_u32(sB[1]), smem_u32(sB[2])};

    // staging role: threads 0-127 -> A row t, 128-255 -> B row t-128
    const bool isA = tid < 128;
    const int srow = isA ? tid : tid - 128;
    const int swz = (srow >> 1) & 3;
    const __nv_bfloat16* gRow = isA ? A3 + (size_t)(m0 + srow) * F
                                    : B3 + (size_t)(n0 + srow) * F;

    // precomputed ldmatrix offsets (validated R12 fragment mapping)
    const int jj0 = lane >> 4;
    uint32_t ofsA[4][2], ofsB[2][2];
#pragma unroll
    for (int mf = 0; mf < 4; mf++) {
        int r = wm * 64 + mf * 16 + (lane & 15);
#pragma unroll
        for (int ks = 0; ks < 2; ks++) {
            int jj = jj0 + 2 * ks;
            ofsA[mf][ks] = r * 64 + ((jj ^ ((r >> 1) & 3)) << 4);
        }
    }
#pragma unroll
    for (int nh = 0; nh < 2; nh++) {
        int r = wn * 32 + nh * 16 + (lane & 15);
#pragma unroll
        for (int ks = 0; ks < 2; ks++) {
            int jj = jj0 + 2 * ks;
            ofsB[nh][ks] = r * 64 + ((jj ^ ((r >> 1) & 3)) << 4);
        }
    }

    float acc[4][4][4];
#pragma unroll
    for (int i = 0; i < 4; i++)
#pragma unroll
        for (int j = 0; j < 4; j++)
#pragma unroll
            for (int k = 0; k < 4; k++) acc[i][j][k] = 0.0f;

    // stage(chunk, st): 4x cp.async16 per thread + commit
#define STAGE(chunk, st) do {                                                  \
        int _p = (chunk) >> 4, _kc = (chunk) & 15;                             \
        const __nv_bfloat16* _src = gRow +                                     \
            (isA ? pa[_p] * AS : pb[_p] * BS) + _kc * 32;                      \
        uint32_t _dst = (isA ? sAu[st] : sBu[st]) + srow * 64;                 \
        _Pragma("unroll")                                                      \
        for (int _j = 0; _j < 4; _j++)                                         \
            cp_async16(_dst + ((_j ^ swz) << 4), (const char*)_src + _j * 16); \
        cp_commit();                                                           \
    } while (0)

    STAGE(0, 0);
    STAGE(1, 1);

#pragma unroll 1
    for (int i = 0; i < NCH; i++) {
        if (i == NCH - 1) cp_wait<0>(); else cp_wait<1>();
        __syncthreads();
        if (i + 2 < NCH) {
            int st = i + 2 - ((i + 2) / 3) * 3;
            STAGE(i + 2, st);
        }
        const int buf = i - (i / 3) * 3;
        const uint32_t aB = sAu[buf], bB = sBu[buf];
#pragma unroll
        for (int ks = 0; ks < 2; ks++) {
            uint32_t a[4][4], b[4][2];
#pragma unroll
            for (int mf = 0; mf < 4; mf++)
                ldm_x4(aB + ofsA[mf][ks], a[mf][0], a[mf][1], a[mf][2], a[mf][3]);
#pragma unroll
            for (int nh = 0; nh < 2; nh++) {
                uint32_t r0, r1, r2, r3;
                ldm_x4(bB + ofsB[nh][ks], r0, r1, r2, r3);
                b[nh * 2 + 0][0] = r0; b[nh * 2 + 0][1] = r2;
                b[nh * 2 + 1][0] = r1; b[nh * 2 + 1][1] = r3;
            }
#pragma unroll
            for (int mf = 0; mf < 4; mf++)
#pragma unroll
                for (int nb = 0; nb < 4; nb++)
                    mma16816(acc[mf][nb], a[mf], b[nb]);
        }
    }
#undef STAGE

    // epilogue
    const int g = lane >> 2, tg = lane & 3;
#pragma unroll
    for (int mf = 0; mf < 4; mf++) {
        int row = m0 + wm * 64 + mf * 16 + g;
#pragma unroll
        for (int nb = 0; nb < 4; nb++) {
            int col = n0 + wn * 32 + nb * 8 + tg * 2;
            float b0 = 0.0f, b1 = 0.0f;
            if (bias) { b0 = bias[col]; b1 = bias[col + 1]; }
            float2 v0 = make_float2(acc[mf][nb][0] + b0, acc[mf][nb][1] + b1);
            float2 v1 = make_float2(acc[mf][nb][2] + b0, acc[mf][nb][3] + b1);
            *(float2*)(C + (size_t)row * F + col)       = v0;
            *(float2*)(C + (size_t)(row + 8) * F + col) = v1;
        }
    }
}

// ---------------- 1. adjacency -> ELL ----------------------------------------
__global__ __launch_bounds__(128) void build_ell(const float* __restrict__ adj) {
    int warp_id = blockIdx.x * (blockDim.x >> 5) + (threadIdx.x >> 5);
    if (warp_id >= NROWS) return;
    int lane = threadIdx.x & 31;
    const float* ar = adj + (size_t)warp_id * NROWS;
    int cnt = 0;
    int* crow = g_col + warp_id * ELLW;
    for (int b = 0; b < NROWS; b += 128) {
        float v0 = ar[b + lane];
        float v1 = ar[b + 32 + lane];
        float v2 = ar[b + 64 + lane];
        float v3 = ar[b + 96 + lane];
        unsigned m0 = __ballot_sync(0xFFFFFFFFu, v0 != 0.0f);
        unsigned m1 = __ballot_sync(0xFFFFFFFFu, v1 != 0.0f);
        unsigned m2 = __ballot_sync(0xFFFFFFFFu, v2 != 0.0f);
        unsigned m3 = __ballot_sync(0xFFFFFFFFu, v3 != 0.0f);
        unsigned lm = (1u << lane) - 1u;
        if (v0 != 0.0f) { int p = cnt + __popc(m0 & lm); if (p < ELLW) crow[p] = b + lane; }
        cnt += __popc(m0);
        if (v1 != 0.0f) { int p = cnt + __popc(m1 & lm); if (p < ELLW) crow[p] = b + 32 + lane; }
        cnt += __popc(m1);
        if (v2 != 0.0f) { int p = cnt + __popc(m2 & lm); if (p < ELLW) crow[p] = b + 64 + lane; }
        cnt += __popc(m2);
        if (v3 != 0.0f) { int p = cnt + __popc(m3 & lm); if (p < ELLW) crow[p] = b + 96 + lane; }
        cnt += __popc(m3);
    }
    if (lane == 0) g_len[warp_id] = cnt < ELLW ? cnt : ELLW;
}

// ---------------- 2b. N = Kw @ Qw^T ------------------------------------------
__global__ __launch_bounds__(256) void gemm_abt512(const float* __restrict__ A,
                                                   const float* __restrict__ B,
                                                   float* __restrict__ C) {
    __shared__ float As[64][33];
    __shared__ float Bs[64][33];
    const int t = threadIdx.x;
    const int tx = t & 15, ty = t >> 4;
    const int m0 = blockIdx.y * 64, n0 = blockIdx.x * 64;
    float acc[4][4];
#pragma unroll
    for (int i = 0; i < 4; i++)
#pragma unroll
        for (int j = 0; j < 4; j++) acc[i][j] = 0.0f;

    for (int kt = 0; kt < F; kt += 32) {
#pragma unroll
        for (int r = 0; r < 8; r++) {
            int idx = t + r * 256;
            int row = idx >> 5, k = idx & 31;
            As[row][k] = A[(size_t)(m0 + row) * F + kt + k];
            Bs[row][k] = B[(size_t)(n0 + row) * F + kt + k];
        }
        __syncthreads();
#pragma unroll
        for (int k = 0; k < 32; k++) {
            float a[4], b[4];
#pragma unroll
            for (int i = 0; i < 4; i++) a[i] = As[ty * 4 + i][k];
#pragma unroll
            for (int j = 0; j < 4; j++) b[j] = Bs[tx * 4 + j][k];
#pragma unroll
            for (int i = 0; i < 4; i++)
#pragma unroll
                for (int j = 0; j < 4; j++) acc[i][j] = fmaf(a[i], b[j], acc[i][j]);
        }
        __syncthreads();
    }
#pragma unroll
    for (int i = 0; i < 4; i++)
#pragma unroll
        for (int j = 0; j < 4; j++)
            C[(size_t)(m0 + ty * 4 + i) * F + n0 + tx * 4 + j] = acc[i][j];
}

// ---------------- 2c. u, v, c ------------------------------------------------
__global__ __launch_bounds__(256) void uvc_kernel(const float* __restrict__ Qw,
                                                  const float* __restrict__ Qb,
                                                  const float* __restrict__ Kw,
                                                  const float* __restrict__ Kb) {
    int t = threadIdx.x;
    int warp = t >> 5, lane = t & 31;
    int b = blockIdx.x;
    if (b < 128) {
        bool do_u = (b < 64);
        int row = (do_u ? b : b - 64) * 8 + warp;
        const float* W   = do_u ? Qw : Kw;
        const float* vec = do_u ? Kb : Qb;
        const float* wr = W + (size_t)row * F;
        float s = 0.0f;
#pragma unroll 4
        for (int k = lane; k < F; k += 32) s += wr[k] * vec[k];
#pragma unroll
        for (int o = 16; o > 0; o >>= 1) s += __shfl_xor_sync(0xFFFFFFFFu, s, o);
        if (lane == 0) (do_u ? g_u : g_v)[row] = s;
    } else {
        __shared__ float red[256];
        float s = Qb[t] * Kb[t] + Qb[t + 256] * Kb[t + 256];
        red[t] = s;
        __syncthreads();
        for (int o = 128; o > 0; o >>= 1) {
            if (t < o) red[t] += red[t + o];
            __syncthreads();
        }
        if (t == 0) g_c = red[0];
    }
}

// ---------------- 3. h = relu(adj@XW + b), fused b_j = h_j.v -----------------
__global__ __launch_bounds__(128) void spmm_relu_bvec(const float* __restrict__ XW,
                                                      const float* __restrict__ bias,
                                                      float* __restrict__ H) {
    __shared__ float red[128];
    int row = blockIdx.x, t = threadIdx.x;
    int len = g_len[row];
    const int* cols = g_col + row * ELLW;
    float4 a0 = make_float4(0, 0, 0, 0), a1 = make_float4(0, 0, 0, 0);
    float4 a2 = make_float4(0, 0, 0, 0), a3 = make_float4(0, 0, 0, 0);
    int e = 0;
    for (; e + 3 < len; e += 4) {
        int j0 = __ldg(cols + e),     j1 = __ldg(cols + e + 1);
        int j2 = __ldg(cols + e + 2), j3 = __ldg(cols + e + 3);
        float4 v0 = *(const float4*)(XW + (size_t)j0 * F + (t << 2));
        float4 v1 = *(const float4*)(XW + (size_t)j1 * F + (t << 2));
        float4 v2 = *(const float4*)(XW + (size_t)j2 * F + (t << 2));
        float4 v3 = *(const float4*)(XW + (size_t)j3 * F + (t << 2));
        a0.x += v0.x; a0.y += v0.y; a0.z += v0.z; a0.w += v0.w;
        a1.x += v1.x; a1.y += v1.y; a1.z += v1.z; a1.w += v1.w;
        a2.x += v2.x; a2.y += v2.y; a2.z += v2.z; a2.w += v2.w;
        a3.x += v3.x; a3.y += v3.y; a3.z += v3.z; a3.w += v3.w;
    }
    for (; e < len; e++) {
        int j0 = __ldg(cols + e);
        float4 v0 = *(const float4*)(XW + (size_t)j0 * F + (t << 2));
        a0.x += v0.x; a0.y += v0.y; a0.z += v0.z; a0.w += v0.w;
    }
    float4 b4 = *(const float4*)(bias + (t << 2));
    float4 o;
    o.x = fmaxf((a0.x + a1.x) + (a2.x + a3.x) + b4.x, 0.0f);
    o.y = fmaxf((a0.y + a1.y) + (a2.y + a3.y) + b4.y, 0.0f);
    o.z = fmaxf((a0.z + a1.z) + (a2.z + a3.z) + b4.z, 0.0f);
    o.w = fmaxf((a0.w + a1.w) + (a2.w + a3.w) + b4.w, 0.0f);
    *(float4*)(H + (size_t)row * F + (t << 2)) = o;

    float4 v4 = ((const float4*)g_v)[t];
    red[t] = o.x * v4.x + o.y * v4.y + o.z * v4.z + o.w * v4.w;
    __syncthreads();
    for (int s = 64; s > 0; s >>= 1) {
        if (t < s) red[t] += red[t + s];
        __syncthreads();
    }
    if (t == 0) g_bv[row] = red[0];
}

// ---------------- 4. edge scores + masked softmax ----------------------------
__global__ __launch_bounds__(256) void scores_softmax(const float* __restrict__ H,
                                                      const float* __restrict__ R) {
    __shared__ float4 qs[128];
    __shared__ float sc[ELLW];
    __shared__ float red[256];
    __shared__ float sA;
    int row = blockIdx.x, t = threadIdx.x;
    if (t < 128) qs[t] = *(const float4*)(H + (size_t)row * F + (t << 2));
    __syncthreads();

    float ap = 0.0f;
    if (t < 128) {
        float4 q = qs[t];
        float4 uu = ((const float4*)g_u)[t];
        ap = q.x * uu.x + q.y * uu.y + q.z * uu.z + q.w * uu.w;
    }
    red[t] = ap;
    __syncthreads();
    for (int s = 128; s > 0; s >>= 1) {
        if (t < s) red[t] += red[t + s];
        __syncthreads();
    }
    if (t == 0) sA = red[0] + g_c;
    __syncthreads();
    float abase = sA;

    int len = g_len[row];
    int lane = t & 31, w = t >> 5;
    const int* cols = g_col + row * ELLW;
    for (int e = w; e < len; e += 8) {
        int j = __ldg(cols + e);
        const float4* kr = (const float4*)(R + (size_t)j * F);
        float s = 0.0f;
#pragma unroll
        for (int q = 0; q < 4; q++) {
            float4 kv = kr[lane + 32 * q];
            float4 qv = qs[lane + 32 * q];
            s += kv.x * qv.x + kv.y * qv.y + kv.z * qv.z + kv.w * qv.w;
        }
#pragma unroll
        for (int o = 16; o > 0; o >>= 1) s += __shfl_xor_sync(0xFFFFFFFFu, s, o);
        if (lane == 0) sc[e] = s + abase + g_bv[j];
    }
    __syncthreads();

    red[t] = (t < len) ? sc[t] : -INFINITY;
    __syncthreads();
    for (int s = 128; s > 0; s >>= 1) {
        if (t < s) red[t] = fmaxf(red[t], red[t + s]);
        __syncthreads();
    }
    float m = fmaxf(red[0], 0.0f);
    __syncthreads();

    float ez = (t < len) ? expf(sc[t] - m) : 0.0f;
    red[t] = ez;
    __syncthreads();
    for (int s = 128; s > 0; s >>= 1) {
        if (t < s) red[t] += red[t + s];
        __syncthreads();
    }
    float em = expf(-m);
    float Z = red[0] + (float)(NROWS - len) * em;
    float w0 = em / Z;
    if (t < len) g_w[row * ELLW + t] = ez / Z - w0;
    if (t == 0) g_w0[row] = w0;
}

// ---------------- 5. column sums of Vh ---------------------------------------
__global__ __launch_bounds__(512) void colsum_part(const float* __restrict__ V) {
    int b = blockIdx.x, c = threadIdx.x;
    const float* base = V + (size_t)b * 256 * F + c;
    float s0 = 0, s1 = 0, s2 = 0, s3 = 0;
#pragma unroll 4
    for (int r = 0; r < 256; r += 4) {
        s0 += base[(size_t)(r + 0) * F];
        s1 += base[(size_t)(r + 1) * F];
        s2 += base[(size_t)(r + 2) * F];
        s3 += base[(size_t)(r + 3) * F];
    }
    g_part[b * F + c] = (s0 + s1) + (s2 + s3);
}
__global__ __launch_bounds__(512) void colsum_final() {
    int c = threadIdx.x;
    float s = 0.0f;
#pragma unroll
    for (int b = 0; b < 32; b++) s += g_part[b * F + c];
    g_csum[c] = s;
}

// ---------------- 6. X_tilde = attention @ Vh, fused LayerNorm ---------------
__global__ __launch_bounds__(128) void xt_layernorm(const float* __restrict__ V,
                                                    const float* __restrict__ lng,
                                                    const float* __restrict__ lnb,
                                                    float* __restrict__ Xt) {
    __shared__ float red[128];
    int row = blockIdx.x, t = threadIdx.x;
    int len = g_len[row];
    float w0 = g_w0[row];
    const int* cols = g_col + row * ELLW;
    const float* wts = g_w + row * ELLW;

    float4 cs = ((const float4*)g_csum)[t];
    float4 a0 = make_float4(w0 * cs.x, w0 * cs.y, w0 * cs.z, w0 * cs.w);
    float4 a1 = make_float4(0, 0, 0, 0);
    float4 a2 = make_float4(0, 0, 0, 0);
    float4 a3 = make_float4(0, 0, 0, 0);
    int e = 0;
    for (; e + 3 < len; e += 4) {
        int j0 = __ldg(cols + e),     j1 = __ldg(cols + e + 1);
        int j2 = __ldg(cols + e + 2), j3 = __ldg(cols + e + 3);
        float w_0 = __ldg(wts + e),     w_1 = __ldg(wts + e + 1);
        float w_2 = __ldg(wts + e + 2), w_3 = __ldg(wts + e + 3);
        float4 v0 = *(const float4*)(V + (size_t)j0 * F + (t << 2));
        float4 v1 = *(const float4*)(V + (size_t)j1 * F + (t << 2));
        float4 v2 = *(const float4*)(V + (size_t)j2 * F + (t << 2));
        float4 v3 = *(const float4*)(V + (size_t)j3 * F + (t << 2));
        a0.x += w_0 * v0.x; a0.y += w_0 * v0.y; a0.z += w_0 * v0.z; a0.w += w_0 * v0.w;
        a1.x += w_1 * v1.x; a1.y += w_1 * v1.y; a1.z += w_1 * v1.z; a1.w += w_1 * v1.w;
        a2.x += w_2 * v2.x; a2.y += w_2 * v2.y; a2.z += w_2 * v2.z; a2.w += w_2 * v2.w;
        a3.x += w_3 * v3.x; a3.y += w_3 * v3.y; a3.z += w_3 * v3.z; a3.w += w_3 * v3.w;
    }
    for (; e < len; e++) {
        int j0 = __ldg(cols + e);
        float w_0 = __ldg(wts + e);
        float4 v0 = *(const float4*)(V + (size_t)j0 * F + (t << 2));
        a0.x += w_0 * v0.x; a0.y += w_0 * v0.y; a0.z += w_0 * v0.z; a0.w += w_0 * v0.w;
    }
    float4 x;
    x.x = (a0.x + a1.x) + (a2.x + a3.x);
    x.y = (a0.y + a1.y) + (a2.y + a3.y);
    x.z = (a0.z + a1.z) + (a2.z + a3.z);
    x.w = (a0.w + a1.w) + (a2.w + a3.w);

    red[t] = x.x + x.y + x.z + x.w;
    __syncthreads();
    for (int s = 64; s > 0; s >>= 1) {
        if (t < s) red[t] += red[t + s];
        __syncthreads();
    }
    float mu = red[0] * (1.0f / F);
    __syncthreads();
    float dx = x.x - mu, dy = x.y - mu, dz = x.z - mu, dw = x.w - mu;
    red[t] = dx * dx + dy * dy + dz * dz + dw * dw;
    __syncthreads();
    for (int s = 64; s > 0; s >>= 1) {
        if (t < s) red[t] += red[t + s];
        __syncthreads();
    }
    float inv = rsqrtf(red[0] * (1.0f / F) + 1e-5f);

    float4 g4 = *(const float4*)(lng + (t << 2));
    float4 b4 = *(const float4*)(lnb + (t << 2));
    float4 o;
    o.x = dx * inv * g4.x + b4.x;
    o.y = dy * inv * g4.y + b4.y;
    o.z = dz * inv * g4.z + b4.z;
    o.w = dw * inv * g4.w + b4.w;
    *(float4*)(Xt + (size_t)row * F + (t << 2)) = o;
}

// ---------------- 7. Y = Xt @ gcn2_W -----------------------------------------
__global__ __launch_bounds__(256) void ygemm(const float* __restrict__ Xt,
                                             const float* __restrict__ W2,
                                             float* __restrict__ Y) {
    __shared__ float w2t[NCLS * F];
    int t = threadIdx.x;
    for (int i = t; i < NCLS * F; i += 256) {
        int c = i / F, k = i - c * F;
        w2t[i] = W2[k * NCLS + c];
    }
    __syncthreads();
    int warp = t >> 5, lane = t & 31;
    int row = blockIdx.x * 8 + warp;
    float p[NCLS];
#pragma unroll
    for (int c = 0; c < NCLS; c++) p[c] = 0.0f;
    const float* xr = Xt + (size_t)row * F;
    for (int k = lane; k < F; k += 32) {
        float xv = xr[k];
#pragma unroll
        for (int c = 0; c < NCLS; c++) p[c] += xv * w2t[c * F + k];
    }
#pragma unroll
    for (int c = 0; c < NCLS; c++) {
#pragma unroll
        for (int o = 16; o > 0; o >>= 1) p[c] += __shfl_xor_sync(0xFFFFFFFFu, p[c], o);
    }
    if (lane == 0) {
#pragma unroll
        for (int c = 0; c < NCLS; c++) Y[row * NCLS + c] = p[c];
    }
}

// ---------------- 8. z = adj @ Y + b2, row softmax ---------------------------
__global__ __launch_bounds__(256) void z_softmax(const float* __restrict__ Y,
                                                 const float* __restrict__ b2,
                                                 float* __restrict__ out) {
    int t = threadIdx.x;
    int row = blockIdx.x * 32 + (t >> 3);
    int c = t & 7;
    int len = g_len[row];
    const int* cols = g_col + row * ELLW;
    float acc = b2[c];
    for (int e = 0; e < len; e++) acc += __ldg(Y + __ldg(cols + e) * NCLS + c);
    float m = acc;
#pragma unroll
    for (int o = 4; o > 0; o >>= 1) m = fmaxf(m, __shfl_xor_sync(0xFFFFFFFFu, m, o));
    float ez = expf(acc - m);
    float s = ez;
#pragma unroll
    for (int o = 4; o > 0; o >>= 1) s += __shfl_xor_sync(0xFFFFFFFFu, s, o);
    out[row * NCLS + c] = ez / s;
}

// ---------------- launcher ---------------------------------------------------
extern "C" void kernel_launch(void* const* d_in, const int* in_sizes, int n_in,
                              void* d_out, int out_size) {
    const float* adj    = (const float*)d_in[0];
    const float* x      = (const float*)d_in[1];
    const float* gcn1_W = (const float*)d_in[2];
    const float* gcn1_b = (const float*)d_in[3];
    const float* Qw     = (const float*)d_in[4];
    const float* Qb     = (const float*)d_in[5];
    const float* Kw     = (const float*)d_in[6];
    const float* Kb     = (const float*)d_in[7];
    const float* Vw     = (const float*)d_in[8];
    const float* Vb     = (const float*)d_in[9];
    const float* ln_g   = (const float*)d_in[10];
    const float* ln_b   = (const float*)d_in[11];
    const float* gcn2_W = (const float*)d_in[12];
    const float* gcn2_b = (const float*)d_in[13];
    float* out = (float*)d_out;

    float *XW, *H, *R, *V, *Xt, *Y, *N;
    __nv_bfloat16 *xs, *hs, *g1t, *vwt, *nts;
    cudaGetSymbolAddress((void**)&XW, g_XW);
    cudaGetSymbolAddress((void**)&H,  g_h);
    cudaGetSymbolAddress((void**)&R,  g_R);
    cudaGetSymbolAddress((void**)&V,  g_V);
    cudaGetSymbolAddress((void**)&Xt, g_Xt);
    cudaGetSymbolAddress((void**)&Y,  g_Y);
    cudaGetSymbolAddress((void**)&N,  g_N);
    cudaGetSymbolAddress((void**)&xs,  g_xs);
    cudaGetSymbolAddress((void**)&hs,  g_hs);
    cudaGetSymbolAddress((void**)&g1t, g_g1t);
    cudaGetSymbolAddress((void**)&vwt, g_vwt);
    cudaGetSymbolAddress((void**)&nts, g_nts);

    static cudaStream_t s1 = nullptr;
    static cudaEvent_t evFork = nullptr, evPrep = nullptr, evR = nullptr, evSc = nullptr;
    if (!s1) {
        cudaStreamCreateWithFlags(&s1, cudaStreamNonBlocking);
        cudaEventCreateWithFlags(&evFork, cudaEventDisableTiming);
        cudaEventCreateWithFlags(&evPrep, cudaEventDisableTiming);
        cudaEventCreateWithFlags(&evR,    cudaEventDisableTiming);
        cudaEventCreateWithFlags(&evSc,   cudaEventDisableTiming);
    }

    const int NEL = NROWS * F;
    dim3 mg(F / 128, NROWS / 128);

    cudaEventRecord(evFork, 0);
    cudaStreamWaitEvent(s1, evFork, 0);

    // stream 0: adjacency scan (HBM-bound)
    build_ell<<<NROWS / 4, 128, 0, 0>>>(adj);

    // stream 1: splits + XW GEMM + score-prep (concurrent with build_ell)
    split_plain<<<NEL / 1024, 256, 0, s1>>>(x, xs, NEL);
    split_wt<<<dim3(16, 16), dim3(32, 32), 0, s1>>>(gcn1_W, g1t);
    mma_gemm<<<mg, 256, 0, s1>>>(xs, g1t, nullptr, XW);
    gemm_abt512<<<dim3(8, 8), 256, 0, s1>>>(Kw, Qw, N);
    split_wt<<<dim3(16, 16), dim3(32, 32), 0, s1>>>(N, nts);
    split_wt<<<dim3(16, 16), dim3(32, 32), 0, s1>>>(Vw, vwt);
    uvc_kernel<<<129, 256, 0, s1>>>(Qw, Qb, Kw, Kb);
    cudaEventRecord(evPrep, s1);
    cudaStreamWaitEvent(0, evPrep, 0);

    // join: needs ELL + XW + v
    spmm_relu_bvec<<<NROWS, 128, 0, 0>>>(XW, gcn1_b, H);
    split_plain<<<NEL / 1024, 256, 0, 0>>>(H, hs, NEL);

    mma_gemm<<<mg, 256, 0, 0>>>(hs, nts, nullptr, R);
    cudaEventRecord(evR, 0);
    cudaStreamWaitEvent(s1, evR, 0);
    scores_softmax<<<NROWS, 256, 0, s1>>>(H, R);      // overlaps V-GEMM
    mma_gemm<<<mg, 256, 0, 0>>>(hs, vwt, Vb, V);
    colsum_part<<<32, 512, 0, 0>>>(V);
    colsum_final<<<1, 512, 0, 0>>>();
    cudaEventRecord(evSc, s1);
    cudaStreamWaitEvent(0, evSc, 0);

    xt_layernorm<<<NROWS, 128, 0, 0>>>(V, ln_g, ln_b, Xt);
    ygemm<<<NROWS / 8, 256, 0, 0>>>(Xt, gcn2_W, Y);
    z_softmax<<<NROWS / 32, 256, 0, 0>>>(Y, gcn2_b, out);
}

// round 14
// speedup vs baseline: 1.2191x; 1.2191x over previous
#include <cuda_runtime.h>
#include <math.h>
#include <stdint.h>

#define NROWS 8192
#define F     512
#define NCLS  8
#define ELLW  192

// ---------------- static scratch (device globals; no runtime alloc) ----------
__device__ __align__(16) float g_XW[NROWS * F];
__device__ __align__(16) float g_h [NROWS * F];
__device__ __align__(16) float g_R [NROWS * F];   // R = h @ N
__device__ __align__(16) float g_V [NROWS * F];
__device__ __align__(16) float g_Xt[NROWS * F];
__device__ __align__(16) float g_Y [NROWS * NCLS];
__device__ __align__(16) float g_N [F * F];       // N = Kw @ Qw^T
__device__ __align__(16) float g_u [F];           // u = Qw @ Kb
__device__ __align__(16) float g_v [F];           // v = Kw @ Qb
__device__ float g_c;                             // c = Qb . Kb
__device__ float g_bv[NROWS];                     // b_j = h_j . v
__device__ int   g_col[NROWS * ELLW];
__device__ int   g_len[NROWS];
__device__ float g_w  [NROWS * ELLW];
__device__ float g_w0 [NROWS];
__device__ __align__(16) float g_csum[F];
__device__ float g_part[32 * F];

// ---------------- packed f32x2 helpers (Blackwell FFMA2 path) ----------------
__device__ __forceinline__ unsigned long long pk2(float x, float y) {
    unsigned long long r;
    asm("mov.b64 %0, {%1, %2};" : "=l"(r) : "f"(x), "f"(y));
    return r;
}
__device__ __forceinline__ float2 upk2(unsigned long long v) {
    float2 r;
    asm("mov.b64 {%0, %1}, %2;" : "=f"(r.x), "=f"(r.y) : "l"(v));
    return r;
}
__device__ __forceinline__ void fma2(unsigned long long& d,
                                     unsigned long long a,
                                     unsigned long long b) {
    asm("fma.rn.f32x2 %0, %1, %2, %0;" : "+l"(d) : "l"(a), "l"(b));
}
__device__ __forceinline__ uint32_t smem_u32(const void* p) {
    uint32_t a;
    asm("{ .reg .u64 t; cvta.to.shared.u64 t, %1; cvt.u32.u64 %0, t; }" : "=r"(a) : "l"(p));
    return a;
}
template <int N> __device__ __forceinline__ void cp_wait() {
    asm volatile("cp.async.wait_group %0;" :: "n"(N));
}
__device__ __forceinline__ void cp_async16(uint32_t dst, const void* src) {
    asm volatile("cp.async.ca.shared.global [%0], [%1], 16;" :: "r"(dst), "l"(src));
}
__device__ __forceinline__ void cp_commit() {
    asm volatile("cp.async.commit_group;");
}

// ---------------- 1. adjacency -> ELL (warp/row, MLP=4, ballot compaction) ---
__global__ __launch_bounds__(128) void build_ell(const float* __restrict__ adj) {
    int warp_id = blockIdx.x * (blockDim.x >> 5) + (threadIdx.x >> 5);
    if (warp_id >= NROWS) return;
    int lane = threadIdx.x & 31;
    const float* ar = adj + (size_t)warp_id * NROWS;
    int cnt = 0;
    int* crow = g_col + warp_id * ELLW;
    for (int b = 0; b < NROWS; b += 128) {
        float v0 = ar[b + lane];
        float v1 = ar[b + 32 + lane];
        float v2 = ar[b + 64 + lane];
        float v3 = ar[b + 96 + lane];
        unsigned m0 = __ballot_sync(0xFFFFFFFFu, v0 != 0.0f);
        unsigned m1 = __ballot_sync(0xFFFFFFFFu, v1 != 0.0f);
        unsigned m2 = __ballot_sync(0xFFFFFFFFu, v2 != 0.0f);
        unsigned m3 = __ballot_sync(0xFFFFFFFFu, v3 != 0.0f);
        unsigned lm = (1u << lane) - 1u;
        if (v0 != 0.0f) { int p = cnt + __popc(m0 & lm); if (p < ELLW) crow[p] = b + lane; }
        cnt += __popc(m0);
        if (v1 != 0.0f) { int p = cnt + __popc(m1 & lm); if (p < ELLW) crow[p] = b + 32 + lane; }
        cnt += __popc(m1);
        if (v2 != 0.0f) { int p = cnt + __popc(m2 & lm); if (p < ELLW) crow[p] = b + 64 + lane; }
        cnt += __popc(m2);
        if (v3 != 0.0f) { int p = cnt + __popc(m3 & lm); if (p < ELLW) crow[p] = b + 96 + lane; }
        cnt += __popc(m3);
    }
    if (lane == 0) g_len[warp_id] = cnt < ELLW ? cnt : ELLW;
}

// ---------------- 2. fp32 SGEMM: FFMA2 + cp.async 3-stage pipeline -----------
// BM=128 BN=128 BK=16, 256 threads, 8x8/thread, A staged [m][20], B [k][128].
// Same arithmetic order as the register-prefetch version (bit-identical C).
__global__ __launch_bounds__(256, 2) void sgemm512(const float* __restrict__ A,
                                                   const float* __restrict__ B,
                                                   const float* __restrict__ bias,
                                                   float* __restrict__ C) {
    __shared__ __align__(16) float As[3][128][20];   // row pad 20 -> 80B (16B-aligned)
    __shared__ __align__(16) float Bs[3][16][128];
    const int tid = threadIdx.x;
    const int bm = blockIdx.y, bn = blockIdx.x;
    const float* Ab = A + (size_t)bm * 128 * F;
    const float* Bb = B + bn * 128;
    const int tx = tid & 15, ty = tid >> 4;

    uint32_t sAu[3] = {smem_u32(As[0]), smem_u32(As[1]), smem_u32(As[2])};
    uint32_t sBu[3] = {smem_u32(Bs[0]), smem_u32(Bs[1]), smem_u32(Bs[2])};

    // staging map: A — 2 threads/row, 2x16B each; B — 16 threads/k-row, 2x16B each
    const int arow = tid >> 1, acn = tid & 1;
    const int brow = tid >> 4, bcn = tid & 15;
    const float* agp = Ab + (size_t)arow * F + acn * 8;
    const float* bgp = Bb + bcn * 8;

#define SGSTAGE(ktile, st) do {                                             \
        const float* _a = agp + (ktile) * 16;                               \
        const float* _b = bgp + (size_t)((ktile) * 16 + brow) * F;          \
        uint32_t _da = sAu[st] + arow * 80 + acn * 32;                      \
        uint32_t _db = sBu[st] + brow * 512 + bcn * 32;                     \
        cp_async16(_da, _a);      cp_async16(_da + 16, _a + 4);             \
        cp_async16(_db, _b);      cp_async16(_db + 16, _b + 4);             \
        cp_commit();                                                        \
    } while (0)

    unsigned long long acc[4][8];
#pragma unroll
    for (int ip = 0; ip < 4; ip++)
#pragma unroll
        for (int j = 0; j < 8; j++) acc[ip][j] = 0ULL;

    SGSTAGE(0, 0);
    SGSTAGE(1, 1);

#pragma unroll 1
    for (int t = 0; t < 32; t++) {
        if (t == 31) cp_wait<0>(); else cp_wait<1>();
        __syncthreads();
        if (t + 2 < 32) {
            int st = (t + 2) % 3;
            SGSTAGE(t + 2, st);
        }
        const int buf = t % 3;
        const float (*Asb)[20] = As[buf];
        const float (*Bsb)[128] = Bs[buf];
#pragma unroll
        for (int k = 0; k < 16; k++) {
            float a0 = Asb[ty * 4 + 0][k], a1 = Asb[ty * 4 + 1][k];
            float a2 = Asb[ty * 4 + 2][k], a3 = Asb[ty * 4 + 3][k];
            float a4 = Asb[64 + ty * 4 + 0][k], a5 = Asb[64 + ty * 4 + 1][k];
            float a6 = Asb[64 + ty * 4 + 2][k], a7 = Asb[64 + ty * 4 + 3][k];
            float4 bv0 = *(const float4*)&Bsb[k][tx * 4];
            float4 bv1 = *(const float4*)&Bsb[k][64 + tx * 4];
            unsigned long long ap[4], bd[8];
            ap[0] = pk2(a0, a1); ap[1] = pk2(a2, a3);
            ap[2] = pk2(a4, a5); ap[3] = pk2(a6, a7);
            bd[0] = pk2(bv0.x, bv0.x); bd[1] = pk2(bv0.y, bv0.y);
            bd[2] = pk2(bv0.z, bv0.z); bd[3] = pk2(bv0.w, bv0.w);
            bd[4] = pk2(bv1.x, bv1.x); bd[5] = pk2(bv1.y, bv1.y);
            bd[6] = pk2(bv1.z, bv1.z); bd[7] = pk2(bv1.w, bv1.w);
#pragma unroll
            for (int ip = 0; ip < 4; ip++)
#pragma unroll
                for (int j = 0; j < 8; j++) fma2(acc[ip][j], ap[ip], bd[j]);
        }
    }
#undef SGSTAGE

    float bb[8];
#pragma unroll
    for (int j = 0; j < 4; j++) {
        bb[j]     = bias ? bias[bn * 128 + tx * 4 + j]      : 0.0f;
        bb[4 + j] = bias ? bias[bn * 128 + 64 + tx * 4 + j] : 0.0f;
    }
#pragma unroll
    for (int ip = 0; ip < 4; ip++) {
        int rbase = (ip < 2) ? (ty * 4 + 2 * ip) : (64 + ty * 4 + 2 * (ip - 2));
        float2 c[8];
#pragma unroll
        for (int j = 0; j < 8; j++) c[j] = upk2(acc[ip][j]);
        {
            int row = bm * 128 + rbase;
            float* Cr = C + (size_t)row * F + bn * 128;
            float4 v0 = make_float4(c[0].x + bb[0], c[1].x + bb[1],
                                    c[2].x + bb[2], c[3].x + bb[3]);
            float4 v1 = make_float4(c[4].x + bb[4], c[5].x + bb[5],
                                    c[6].x + bb[6], c[7].x + bb[7]);
            *(float4*)(Cr + tx * 4)      = v0;
            *(float4*)(Cr + 64 + tx * 4) = v1;
        }
        {
            int row = bm * 128 + rbase + 1;
            float* Cr = C + (size_t)row * F + bn * 128;
            float4 v0 = make_float4(c[0].y + bb[0], c[1].y + bb[1],
                                    c[2].y + bb[2], c[3].y + bb[3]);
            float4 v1 = make_float4(c[4].y + bb[4], c[5].y + bb[5],
                                    c[6].y + bb[6], c[7].y + bb[7]);
            *(float4*)(Cr + tx * 4)      = v0;
            *(float4*)(Cr + 64 + tx * 4) = v1;
        }
    }
}

// ---------------- 2b. N = Kw @ Qw^T ------------------------------------------
__global__ __launch_bounds__(256) void gemm_abt512(const float* __restrict__ A,
                                                   const float* __restrict__ B,
                                                   float* __restrict__ C) {
    __shared__ float As[64][33];
    __shared__ float Bs[64][33];
    const int t = threadIdx.x;
    const int tx = t & 15, ty = t >> 4;
    const int m0 = blockIdx.y * 64, n0 = blockIdx.x * 64;
    float acc[4][4];
#pragma unroll
    for (int i = 0; i < 4; i++)
#pragma unroll
        for (int j = 0; j < 4; j++) acc[i][j] = 0.0f;

    for (int kt = 0; kt < F; kt += 32) {
#pragma unroll
        for (int r = 0; r < 8; r++) {
            int idx = t + r * 256;
            int row = idx >> 5, k = idx & 31;
            As[row][k] = A[(size_t)(m0 + row) * F + kt + k];
            Bs[row][k] = B[(size_t)(n0 + row) * F + kt + k];
        }
        __syncthreads();
#pragma unroll
        for (int k = 0; k < 32; k++) {
            float a[4], b[4];
#pragma unroll
            for (int i = 0; i < 4; i++) a[i] = As[ty * 4 + i][k];
#pragma unroll
            for (int j = 0; j < 4; j++) b[j] = Bs[tx * 4 + j][k];
#pragma unroll
            for (int i = 0; i < 4; i++)
#pragma unroll
                for (int j = 0; j < 4; j++) acc[i][j] = fmaf(a[i], b[j], acc[i][j]);
        }
        __syncthreads();
    }
#pragma unroll
    for (int i = 0; i < 4; i++)
#pragma unroll
        for (int j = 0; j < 4; j++)
            C[(size_t)(m0 + ty * 4 + i) * F + n0 + tx * 4 + j] = acc[i][j];
}

// ---------------- 2c. u = Qw@Kb, v = Kw@Qb, c = Qb.Kb (warp per row) ---------
__global__ __launch_bounds__(256) void uvc_kernel(const float* __restrict__ Qw,
                                                  const float* __restrict__ Qb,
                                                  const float* __restrict__ Kw,
                                                  const float* __restrict__ Kb) {
    int t = threadIdx.x;
    int warp = t >> 5, lane = t & 31;
    int b = blockIdx.x;
    if (b < 128) {
        bool do_u = (b < 64);
        int row = (do_u ? b : b - 64) * 8 + warp;
        const float* W   = do_u ? Qw : Kw;
        const float* vec = do_u ? Kb : Qb;
        const float* wr = W + (size_t)row * F;
        float s = 0.0f;
#pragma unroll 4
        for (int k = lane; k < F; k += 32) s += wr[k] * vec[k];
#pragma unroll
        for (int o = 16; o > 0; o >>= 1) s += __shfl_xor_sync(0xFFFFFFFFu, s, o);
        if (lane == 0) (do_u ? g_u : g_v)[row] = s;
    } else {
        __shared__ float red[256];
        float s = Qb[t] * Kb[t] + Qb[t + 256] * Kb[t + 256];
        red[t] = s;
        __syncthreads();
        for (int o = 128; o > 0; o >>= 1) {
            if (t < o) red[t] += red[t + o];
            __syncthreads();
        }
        if (t == 0) g_c = red[0];
    }
}

// ---------------- 3. h = relu(adj@XW + b), fused b_j = h_j.v -----------------
__global__ __launch_bounds__(128) void spmm_relu_bvec(const float* __restrict__ XW,
                                                      const float* __restrict__ bias,
                                                      float* __restrict__ H) {
    __shared__ float red[128];
    int row = blockIdx.x, t = threadIdx.x;
    int len = g_len[row];
    const int* cols = g_col + row * ELLW;
    float4 a0 = make_float4(0, 0, 0, 0), a1 = make_float4(0, 0, 0, 0);
    float4 a2 = make_float4(0, 0, 0, 0), a3 = make_float4(0, 0, 0, 0);
    int e = 0;
    for (; e + 3 < len; e += 4) {
        int j0 = __ldg(cols + e),     j1 = __ldg(cols + e + 1);
        int j2 = __ldg(cols + e + 2), j3 = __ldg(cols + e + 3);
        float4 v0 = *(const float4*)(XW + (size_t)j0 * F + (t << 2));
        float4 v1 = *(const float4*)(XW + (size_t)j1 * F + (t << 2));
        float4 v2 = *(const float4*)(XW + (size_t)j2 * F + (t << 2));
        float4 v3 = *(const float4*)(XW + (size_t)j3 * F + (t << 2));
        a0.x += v0.x; a0.y += v0.y; a0.z += v0.z; a0.w += v0.w;
        a1.x += v1.x; a1.y += v1.y; a1.z += v1.z; a1.w += v1.w;
        a2.x += v2.x; a2.y += v2.y; a2.z += v2.z; a2.w += v2.w;
        a3.x += v3.x; a3.y += v3.y; a3.z += v3.z; a3.w += v3.w;
    }
    for (; e < len; e++) {
        int j0 = __ldg(cols + e);
        float4 v0 = *(const float4*)(XW + (size_t)j0 * F + (t << 2));
        a0.x += v0.x; a0.y += v0.y; a0.z += v0.z; a0.w += v0.w;
    }
    float4 b4 = *(const float4*)(bias + (t << 2));
    float4 o;
    o.x = fmaxf((a0.x + a1.x) + (a2.x + a3.x) + b4.x, 0.0f);
    o.y = fmaxf((a0.y + a1.y) + (a2.y + a3.y) + b4.y, 0.0f);
    o.z = fmaxf((a0.z + a1.z) + (a2.z + a3.z) + b4.z, 0.0f);
    o.w = fmaxf((a0.w + a1.w) + (a2.w + a3.w) + b4.w, 0.0f);
    *(float4*)(H + (size_t)row * F + (t << 2)) = o;

    // fused: b_row = h_row . v
    float4 v4 = ((const float4*)g_v)[t];
    red[t] = o.x * v4.x + o.y * v4.y + o.z * v4.z + o.w * v4.w;
    __syncthreads();
    for (int s = 64; s > 0; s >>= 1) {
        if (t < s) red[t] += red[t + s];
        __syncthreads();
    }
    if (t == 0) g_bv[row] = red[0];
}

// ---------------- 4. edge scores + masked softmax ----------------------------
__global__ __launch_bounds__(256) void scores_softmax(const float* __restrict__ H,
                                                      const float* __restrict__ R) {
    __shared__ float4 qs[128];
    __shared__ float sc[ELLW];
    __shared__ float red[256];
    __shared__ float sA;
    int row = blockIdx.x, t = threadIdx.x;
    if (t < 128) qs[t] = *(const float4*)(H + (size_t)row * F + (t << 2));
    __syncthreads();

    float ap = 0.0f;
    if (t < 128) {
        float4 q = qs[t];
        float4 uu = ((const float4*)g_u)[t];
        ap = q.x * uu.x + q.y * uu.y + q.z * uu.z + q.w * uu.w;
    }
    red[t] = ap;
    __syncthreads();
    for (int s = 128; s > 0; s >>= 1) {
        if (t < s) red[t] += red[t + s];
        __syncthreads();
    }
    if (t == 0) sA = red[0] + g_c;
    __syncthreads();
    float abase = sA;

    int len = g_len[row];
    int lane = t & 31, w = t >> 5;
    const int* cols = g_col + row * ELLW;
    for (int e = w; e < len; e += 8) {
        int j = __ldg(cols + e);
        const float4* kr = (const float4*)(R + (size_t)j * F);
        float s = 0.0f;
#pragma unroll
        for (int q = 0; q < 4; q++) {
            float4 kv = kr[lane + 32 * q];
            float4 qv = qs[lane + 32 * q];
            s += kv.x * qv.x + kv.y * qv.y + kv.z * qv.z + kv.w * qv.w;
        }
#pragma unroll
        for (int o = 16; o > 0; o >>= 1) s += __shfl_xor_sync(0xFFFFFFFFu, s, o);
        if (lane == 0) sc[e] = s + abase + g_bv[j];
    }
    __syncthreads();

    red[t] = (t < len) ? sc[t] : -INFINITY;
    __syncthreads();
    for (int s = 128; s > 0; s >>= 1) {
        if (t < s) red[t] = fmaxf(red[t], red[t + s]);
        __syncthreads();
    }
    float m = fmaxf(red[0], 0.0f);
    __syncthreads();

    float ez = (t < len) ? expf(sc[t] - m) : 0.0f;
    red[t] = ez;
    __syncthreads();
    for (int s = 128; s > 0; s >>= 1) {
        if (t < s) red[t] += red[t + s];
        __syncthreads();
    }
    float em = expf(-m);
    float Z = red[0] + (float)(NROWS - len) * em;
    float w0 = em / Z;
    if (t < len) g_w[row * ELLW + t] = ez / Z - w0;
    if (t == 0) g_w0[row] = w0;
}

// ---------------- 5. column sums of Vh ---------------------------------------
__global__ __launch_bounds__(512) void colsum_part(const float* __restrict__ V) {
    int b = blockIdx.x, c = threadIdx.x;
    const float* base = V + (size_t)b * 256 * F + c;
    float s0 = 0, s1 = 0, s2 = 0, s3 = 0;
#pragma unroll 4
    for (int r = 0; r < 256; r += 4) {
        s0 += base[(size_t)(r + 0) * F];
        s1 += base[(size_t)(r + 1) * F];
        s2 += base[(size_t)(r + 2) * F];
        s3 += base[(size_t)(r + 3) * F];
    }
    g_part[b * F + c] = (s0 + s1) + (s2 + s3);
}
__global__ __launch_bounds__(512) void colsum_final() {
    int c = threadIdx.x;
    float s = 0.0f;
#pragma unroll
    for (int b = 0; b < 32; b++) s += g_part[b * F + c];
    g_csum[c] = s;
}

// ---------------- 6. X_tilde = attention @ Vh, fused LayerNorm ---------------
__global__ __launch_bounds__(128) void xt_layernorm(const float* __restrict__ V,
                                                    const float* __restrict__ lng,
                                                    const float* __restrict__ lnb,
                                                    float* __restrict__ Xt) {
    __shared__ float red[128];
    int row = blockIdx.x, t = threadIdx.x;
    int len = g_len[row];
    float w0 = g_w0[row];
    const int* cols = g_col + row * ELLW;
    const float* wts = g_w + row * ELLW;

    float4 cs = ((const float4*)g_csum)[t];
    float4 a0 = make_float4(w0 * cs.x, w0 * cs.y, w0 * cs.z, w0 * cs.w);
    float4 a1 = make_float4(0, 0, 0, 0);
    float4 a2 = make_float4(0, 0, 0, 0);
    float4 a3 = make_float4(0, 0, 0, 0);
    int e = 0;
    for (; e + 3 < len; e += 4) {
        int j0 = __ldg(cols + e),     j1 = __ldg(cols + e + 1);
        int j2 = __ldg(cols + e + 2), j3 = __ldg(cols + e + 3);
        float w_0 = __ldg(wts + e),     w_1 = __ldg(wts + e + 1);
        float w_2 = __ldg(wts + e + 2), w_3 = __ldg(wts + e + 3);
        float4 v0 = *(const float4*)(V + (size_t)j0 * F + (t << 2));
        float4 v1 = *(const float4*)(V + (size_t)j1 * F + (t << 2));
        float4 v2 = *(const float4*)(V + (size_t)j2 * F + (t << 2));
        float4 v3 = *(const float4*)(V + (size_t)j3 * F + (t << 2));
        a0.x += w_0 * v0.x; a0.y += w_0 * v0.y; a0.z += w_0 * v0.z; a0.w += w_0 * v0.w;
        a1.x += w_1 * v1.x; a1.y += w_1 * v1.y; a1.z += w_1 * v1.z; a1.w += w_1 * v1.w;
        a2.x += w_2 * v2.x; a2.y += w_2 * v2.y; a2.z += w_2 * v2.z; a2.w += w_2 * v2.w;
        a3.x += w_3 * v3.x; a3.y += w_3 * v3.y; a3.z += w_3 * v3.z; a3.w += w_3 * v3.w;
    }
    for (; e < len; e++) {
        int j0 = __ldg(cols + e);
        float w_0 = __ldg(wts + e);
        float4 v0 = *(const float4*)(V + (size_t)j0 * F + (t << 2));
        a0.x += w_0 * v0.x; a0.y += w_0 * v0.y; a0.z += w_0 * v0.z; a0.w += w_0 * v0.w;
    }
    float4 x;
    x.x = (a0.x + a1.x) + (a2.x + a3.x);
    x.y = (a0.y + a1.y) + (a2.y + a3.y);
    x.z = (a0.z + a1.z) + (a2.z + a3.z);
    x.w = (a0.w + a1.w) + (a2.w + a3.w);

    red[t] = x.x + x.y + x.z + x.w;
    __syncthreads();
    for (int s = 64; s > 0; s >>= 1) {
        if (t < s) red[t] += red[t + s];
        __syncthreads();
    }
    float mu = red[0] * (1.0f / F);
    __syncthreads();
    float dx = x.x - mu, dy = x.y - mu, dz = x.z - mu, dw = x.w - mu;
    red[t] = dx * dx + dy * dy + dz * dz + dw * dw;
    __syncthreads();
    for (int s = 64; s > 0; s >>= 1) {
        if (t < s) red[t] += red[t + s];
        __syncthreads();
    }
    float inv = rsqrtf(red[0] * (1.0f / F) + 1e-5f);

    float4 g4 = *(const float4*)(lng + (t << 2));
    float4 b4 = *(const float4*)(lnb + (t << 2));
    float4 o;
    o.x = dx * inv * g4.x + b4.x;
    o.y = dy * inv * g4.y + b4.y;
    o.z = dz * inv * g4.z + b4.z;
    o.w = dw * inv * g4.w + b4.w;
    *(float4*)(Xt + (size_t)row * F + (t << 2)) = o;
}

// ---------------- 7. Y = Xt @ gcn2_W -----------------------------------------
__global__ __launch_bounds__(256) void ygemm(const float* __restrict__ Xt,
                                             const float* __restrict__ W2,
                                             float* __restrict__ Y) {
    __shared__ float w2t[NCLS * F];
    int t = threadIdx.x;
    for (int i = t; i < NCLS * F; i += 256) {
        int c = i / F, k = i - c * F;
        w2t[i] = W2[k * NCLS + c];
    }
    __syncthreads();
    int warp = t >> 5, lane = t & 31;
    int row = blockIdx.x * 8 + warp;
    float p[NCLS];
#pragma unroll
    for (int c = 0; c < NCLS; c++) p[c] = 0.0f;
    const float* xr = Xt + (size_t)row * F;
    for (int k = lane; k < F; k += 32) {
        float xv = xr[k];
#pragma unroll
        for (int c = 0; c < NCLS; c++) p[c] += xv * w2t[c * F + k];
    }
#pragma unroll
    for (int c = 0; c < NCLS; c++) {
#pragma unroll
        for (int o = 16; o > 0; o >>= 1) p[c] += __shfl_xor_sync(0xFFFFFFFFu, p[c], o);
    }
    if (lane == 0) {
#pragma unroll
        for (int c = 0; c < NCLS; c++) Y[row * NCLS + c] = p[c];
    }
}

// ---------------- 8. z = adj @ Y + b2, row softmax ---------------------------
__global__ __launch_bounds__(256) void z_softmax(const float* __restrict__ Y,
                                                 const float* __restrict__ b2,
                                                 float* __restrict__ out) {
    int t = threadIdx.x;
    int row = blockIdx.x * 32 + (t >> 3);
    int c = t & 7;
    int len = g_len[row];
    const int* cols = g_col + row * ELLW;
    float acc = b2[c];
    for (int e = 0; e < len; e++) acc += __ldg(Y + __ldg(cols + e) * NCLS + c);
    float m = acc;
#pragma unroll
    for (int o = 4; o > 0; o >>= 1) m = fmaxf(m, __shfl_xor_sync(0xFFFFFFFFu, m, o));
    float ez = expf(acc - m);
    float s = ez;
#pragma unroll
    for (int o = 4; o > 0; o >>= 1) s += __shfl_xor_sync(0xFFFFFFFFu, s, o);
    out[row * NCLS + c] = ez / s;
}

// ---------------- launcher: fork-join overlap on two streams -----------------
extern "C" void kernel_launch(void* const* d_in, const int* in_sizes, int n_in,
                              void* d_out, int out_size) {
    const float* adj    = (const float*)d_in[0];
    const float* x      = (const float*)d_in[1];
    const float* gcn1_W = (const float*)d_in[2];
    const float* gcn1_b = (const float*)d_in[3];
    const float* Qw     = (const float*)d_in[4];
    const float* Qb     = (const float*)d_in[5];
    const float* Kw     = (const float*)d_in[6];
    const float* Kb     = (const float*)d_in[7];
    const float* Vw     = (const float*)d_in[8];
    const float* Vb     = (const float*)d_in[9];
    const float* ln_g   = (const float*)d_in[10];
    const float* ln_b   = (const float*)d_in[11];
    const float* gcn2_W = (const float*)d_in[12];
    const float* gcn2_b = (const float*)d_in[13];
    float* out = (float*)d_out;

    float *XW, *H, *R, *V, *Xt, *Y, *N;
    cudaGetSymbolAddress((void**)&XW, g_XW);
    cudaGetSymbolAddress((void**)&H,  g_h);
    cudaGetSymbolAddress((void**)&R,  g_R);
    cudaGetSymbolAddress((void**)&V,  g_V);
    cudaGetSymbolAddress((void**)&Xt, g_Xt);
    cudaGetSymbolAddress((void**)&Y,  g_Y);
    cudaGetSymbolAddress((void**)&N,  g_N);

    static cudaStream_t s1 = nullptr;
    static cudaEvent_t evFork = nullptr, evPrep = nullptr, evR = nullptr, evSc = nullptr;
    if (!s1) {
        cudaStreamCreateWithFlags(&s1, cudaStreamNonBlocking);
        cudaEventCreateWithFlags(&evFork, cudaEventDisableTiming);
        cudaEventCreateWithFlags(&evPrep, cudaEventDisableTiming);
        cudaEventCreateWithFlags(&evR,    cudaEventDisableTiming);
        cudaEventCreateWithFlags(&evSc,   cudaEventDisableTiming);
    }

    dim3 gg(F / 128, NROWS / 128);

    cudaEventRecord(evFork, 0);
    cudaStreamWaitEvent(s1, evFork, 0);

    // stream 0: adjacency scan (HBM-bound)
    build_ell<<<NROWS / 4, 128, 0, 0>>>(adj);
    // stream 1: x@W1 GEMM (FMA-bound) + score-prep algebra, concurrent
    sgemm512<<<gg, 256, 0, s1>>>(x, gcn1_W, nullptr, XW);
    gemm_abt512<<<dim3(8, 8), 256, 0, s1>>>(Kw, Qw, N);   // N = Kw @ Qw^T
    uvc_kernel<<<129, 256, 0, s1>>>(Qw, Qb, Kw, Kb);
    cudaEventRecord(evPrep, s1);
    cudaStreamWaitEvent(0, evPrep, 0);

    // join: needs ELL + XW + v
    spmm_relu_bvec<<<NROWS, 128, 0, 0>>>(XW, gcn1_b, H);

    // R first on stream 0, then fork scores (L2) onto s1 vs V-GEMM (FMA) on 0
    sgemm512<<<gg, 256, 0, 0>>>(H, N, nullptr, R);
    cudaEventRecord(evR, 0);
    cudaStreamWaitEvent(s1, evR, 0);
    scores_softmax<<<NROWS, 256, 0, s1>>>(H, R);          // overlaps V-GEMM
    sgemm512<<<gg, 256, 0, 0>>>(H, Vw, Vb, V);
    colsum_part<<<32, 512, 0, 0>>>(V);
    colsum_final<<<1, 512, 0, 0>>>();
    cudaEventRecord(evSc, s1);
    cudaStreamWaitEvent(0, evSc, 0);

    // join: needs weights (scores) + V + colsum
    xt_layernorm<<<NROWS, 128, 0, 0>>>(V, ln_g, ln_b, Xt);
    ygemm<<<NROWS / 8, 256, 0, 0>>>(Xt, gcn2_W, Y);
    z_softmax<<<NROWS / 32, 256, 0, 0>>>(Y, gcn2_b, out);
}

// round 15
// speedup vs baseline: 1.4005x; 1.1488x over previous
#include <cuda_runtime.h>
#include <math.h>

#define NROWS 8192
#define F     512
#define NCLS  8
#define ELLW  192

// ---------------- static scratch (device globals; no runtime alloc) ----------
__device__ __align__(16) float g_XW[NROWS * F];
__device__ __align__(16) float g_h [NROWS * F];
__device__ __align__(16) float g_R [NROWS * F];   // R = h @ N
__device__ __align__(16) float g_V [NROWS * F];
__device__ __align__(16) float g_Xt[NROWS * F];
__device__ __align__(16) float g_Y [NROWS * NCLS];
__device__ __align__(16) float g_N [F * F];       // N = Kw @ Qw^T
__device__ __align__(16) float g_u [F];           // u = Qw @ Kb
__device__ __align__(16) float g_v [F];           // v = Kw @ Qb
__device__ float g_c;                             // c = Qb . Kb
__device__ float g_bv[NROWS];                     // b_j = h_j . v
__device__ int   g_col[NROWS * ELLW];
__device__ int   g_len[NROWS];
__device__ float g_w  [NROWS * ELLW];
__device__ float g_w0 [NROWS];
__device__ __align__(16) float g_csum[F];
__device__ float g_part[32 * F];

// ---------------- packed f32x2 helpers (Blackwell FFMA2 path) ----------------
__device__ __forceinline__ unsigned long long pk2(float x, float y) {
    unsigned long long r;
    asm("mov.b64 %0, {%1, %2};" : "=l"(r) : "f"(x), "f"(y));
    return r;
}
__device__ __forceinline__ float2 upk2(unsigned long long v) {
    float2 r;
    asm("mov.b64 {%0, %1}, %2;" : "=f"(r.x), "=f"(r.y) : "l"(v));
    return r;
}
__device__ __forceinline__ void fma2(unsigned long long& d,
                                     unsigned long long a,
                                     unsigned long long b) {
    asm("fma.rn.f32x2 %0, %1, %2, %0;" : "+l"(d) : "l"(a), "l"(b));
}

// ---------------- 1. adjacency -> ELL (warp/row, MLP=4, ballot compaction) ---
__global__ __launch_bounds__(128) void build_ell(const float* __restrict__ adj) {
    int warp_id = blockIdx.x * (blockDim.x >> 5) + (threadIdx.x >> 5);
    if (warp_id >= NROWS) return;
    int lane = threadIdx.x & 31;
    const float* ar = adj + (size_t)warp_id * NROWS;
    int cnt = 0;
    int* crow = g_col + warp_id * ELLW;
    for (int b = 0; b < NROWS; b += 128) {
        float v0 = ar[b + lane];
        float v1 = ar[b + 32 + lane];
        float v2 = ar[b + 64 + lane];
        float v3 = ar[b + 96 + lane];
        unsigned m0 = __ballot_sync(0xFFFFFFFFu, v0 != 0.0f);
        unsigned m1 = __ballot_sync(0xFFFFFFFFu, v1 != 0.0f);
        unsigned m2 = __ballot_sync(0xFFFFFFFFu, v2 != 0.0f);
        unsigned m3 = __ballot_sync(0xFFFFFFFFu, v3 != 0.0f);
        unsigned lm = (1u << lane) - 1u;
        if (v0 != 0.0f) { int p = cnt + __popc(m0 & lm); if (p < ELLW) crow[p] = b + lane; }
        cnt += __popc(m0);
        if (v1 != 0.0f) { int p = cnt + __popc(m1 & lm); if (p < ELLW) crow[p] = b + 32 + lane; }
        cnt += __popc(m1);
        if (v2 != 0.0f) { int p = cnt + __popc(m2 & lm); if (p < ELLW) crow[p] = b + 64 + lane; }
        cnt += __popc(m2);
        if (v3 != 0.0f) { int p = cnt + __popc(m3 & lm); if (p < ELLW) crow[p] = b + 96 + lane; }
        cnt += __popc(m3);
    }
    if (lane == 0) g_len[warp_id] = cnt < ELLW ? cnt : ELLW;
}

// ---------------- 2. fp32 SGEMM with packed FFMA2 (R11 champion) -------------
__global__ __launch_bounds__(256, 2) void sgemm512(const float* __restrict__ A,
                                                   const float* __restrict__ B,
                                                   const float* __restrict__ bias,
                                                   float* __restrict__ C) {
    __shared__ float As[2][16][132];
    __shared__ float Bs[2][16][128];
    const int tid = threadIdx.x;
    const int bm = blockIdx.y, bn = blockIdx.x;
    const float* Ab = A + (size_t)bm * 128 * F;
    const float* Bb = B + bn * 128;

    const int arow = tid >> 2, acol = (tid & 3) << 2;
    const int brow = tid >> 5, bcol = (tid & 31) << 2;
    const int tx = tid & 15, ty = tid >> 4;

    float4 pa0, pa1, pb0, pb1;
    pa0 = *(const float4*)(Ab + (size_t)arow * F + acol);
    pa1 = *(const float4*)(Ab + (size_t)(arow + 64) * F + acol);
    pb0 = *(const float4*)(Bb + (size_t)brow * F + bcol);
    pb1 = *(const float4*)(Bb + (size_t)(brow + 8) * F + bcol);

    unsigned long long acc[4][8];
#pragma unroll
    for (int ip = 0; ip < 4; ip++)
#pragma unroll
        for (int j = 0; j < 8; j++) acc[ip][j] = 0ULL;

    As[0][acol + 0][arow] = pa0.x; As[0][acol + 1][arow] = pa0.y;
    As[0][acol + 2][arow] = pa0.z; As[0][acol + 3][arow] = pa0.w;
    As[0][acol + 0][arow + 64] = pa1.x; As[0][acol + 1][arow + 64] = pa1.y;
    As[0][acol + 2][arow + 64] = pa1.z; As[0][acol + 3][arow + 64] = pa1.w;
    *(float4*)(&Bs[0][brow][bcol])     = pb0;
    *(float4*)(&Bs[0][brow + 8][bcol]) = pb1;
    __syncthreads();

    int buf = 0;
#pragma unroll 1
    for (int kt = 16; kt <= F; kt += 16) {
        if (kt < F) {
            pa0 = *(const float4*)(Ab + (size_t)arow * F + kt + acol);
            pa1 = *(const float4*)(Ab + (size_t)(arow + 64) * F + kt + acol);
            pb0 = *(const float4*)(Bb + (size_t)(kt + brow) * F + bcol);
            pb1 = *(const float4*)(Bb + (size_t)(kt + brow + 8) * F + bcol);
        }
#pragma unroll
        for (int k = 0; k < 16; k++) {
            float4 av0 = *(const float4*)(&As[buf][k][ty * 4]);
            float4 av1 = *(const float4*)(&As[buf][k][64 + ty * 4]);
            float4 bv0 = *(const float4*)(&Bs[buf][k][tx * 4]);
            float4 bv1 = *(const float4*)(&Bs[buf][k][64 + tx * 4]);
            unsigned long long ap[4], bd[8];
            ap[0] = pk2(av0.x, av0.y); ap[1] = pk2(av0.z, av0.w);
            ap[2] = pk2(av1.x, av1.y); ap[3] = pk2(av1.z, av1.w);
            bd[0] = pk2(bv0.x, bv0.x); bd[1] = pk2(bv0.y, bv0.y);
            bd[2] = pk2(bv0.z, bv0.z); bd[3] = pk2(bv0.w, bv0.w);
            bd[4] = pk2(bv1.x, bv1.x); bd[5] = pk2(bv1.y, bv1.y);
            bd[6] = pk2(bv1.z, bv1.z); bd[7] = pk2(bv1.w, bv1.w);
#pragma unroll
            for (int ip = 0; ip < 4; ip++)
#pragma unroll
                for (int j = 0; j < 8; j++) fma2(acc[ip][j], ap[ip], bd[j]);
        }
        if (kt < F) {
            int nb = buf ^ 1;
            As[nb][acol + 0][arow] = pa0.x; As[nb][acol + 1][arow] = pa0.y;
            As[nb][acol + 2][arow] = pa0.z; As[nb][acol + 3][arow] = pa0.w;
            As[nb][acol + 0][arow + 64] = pa1.x; As[nb][acol + 1][arow + 64] = pa1.y;
            As[nb][acol + 2][arow + 64] = pa1.z; As[nb][acol + 3][arow + 64] = pa1.w;
            *(float4*)(&Bs[nb][brow][bcol])     = pb0;
            *(float4*)(&Bs[nb][brow + 8][bcol]) = pb1;
            __syncthreads();
            buf = nb;
        }
    }

    float bb[8];
#pragma unroll
    for (int j = 0; j < 4; j++) {
        bb[j]     = bias ? bias[bn * 128 + tx * 4 + j]      : 0.0f;
        bb[4 + j] = bias ? bias[bn * 128 + 64 + tx * 4 + j] : 0.0f;
    }
#pragma unroll
    for (int ip = 0; ip < 4; ip++) {
        int rbase = (ip < 2) ? (ty * 4 + 2 * ip) : (64 + ty * 4 + 2 * (ip - 2));
        float2 c[8];
#pragma unroll
        for (int j = 0; j < 8; j++) c[j] = upk2(acc[ip][j]);
        {
            int row = bm * 128 + rbase;
            float* Cr = C + (size_t)row * F + bn * 128;
            float4 v0 = make_float4(c[0].x + bb[0], c[1].x + bb[1],
                                    c[2].x + bb[2], c[3].x + bb[3]);
            float4 v1 = make_float4(c[4].x + bb[4], c[5].x + bb[5],
                                    c[6].x + bb[6], c[7].x + bb[7]);
            *(float4*)(Cr + tx * 4)      = v0;
            *(float4*)(Cr + 64 + tx * 4) = v1;
        }
        {
            int row = bm * 128 + rbase + 1;
            float* Cr = C + (size_t)row * F + bn * 128;
            float4 v0 = make_float4(c[0].y + bb[0], c[1].y + bb[1],
                                    c[2].y + bb[2], c[3].y + bb[3]);
            float4 v1 = make_float4(c[4].y + bb[4], c[5].y + bb[5],
                                    c[6].y + bb[6], c[7].y + bb[7]);
            *(float4*)(Cr + tx * 4)      = v0;
            *(float4*)(Cr + 64 + tx * 4) = v1;
        }
    }
}

// ---------------- 2b. N = Kw @ Qw^T ------------------------------------------
__global__ __launch_bounds__(256) void gemm_abt512(const float* __restrict__ A,
                                                   const float* __restrict__ B,
                                                   float* __restrict__ C) {
    __shared__ float As[64][33];
    __shared__ float Bs[64][33];
    const int t = threadIdx.x;
    const int tx = t & 15, ty = t >> 4;
    const int m0 = blockIdx.y * 64, n0 = blockIdx.x * 64;
    float acc[4][4];
#pragma unroll
    for (int i = 0; i < 4; i++)
#pragma unroll
        for (int j = 0; j < 4; j++) acc[i][j] = 0.0f;

    for (int kt = 0; kt < F; kt += 32) {
#pragma unroll
        for (int r = 0; r < 8; r++) {
            int idx = t + r * 256;
            int row = idx >> 5, k = idx & 31;
            As[row][k] = A[(size_t)(m0 + row) * F + kt + k];
            Bs[row][k] = B[(size_t)(n0 + row) * F + kt + k];
        }
        __syncthreads();
#pragma unroll
        for (int k = 0; k < 32; k++) {
            float a[4], b[4];
#pragma unroll
            for (int i = 0; i < 4; i++) a[i] = As[ty * 4 + i][k];
#pragma unroll
            for (int j = 0; j < 4; j++) b[j] = Bs[tx * 4 + j][k];
#pragma unroll
            for (int i = 0; i < 4; i++)
#pragma unroll
                for (int j = 0; j < 4; j++) acc[i][j] = fmaf(a[i], b[j], acc[i][j]);
        }
        __syncthreads();
    }
#pragma unroll
    for (int i = 0; i < 4; i++)
#pragma unroll
        for (int j = 0; j < 4; j++)
            C[(size_t)(m0 + ty * 4 + i) * F + n0 + tx * 4 + j] = acc[i][j];
}

// ---------------- 2c. u = Qw@Kb, v = Kw@Qb, c = Qb.Kb (warp per row) ---------
__global__ __launch_bounds__(256) void uvc_kernel(const float* __restrict__ Qw,
                                                  const float* __restrict__ Qb,
                                                  const float* __restrict__ Kw,
                                                  const float* __restrict__ Kb) {
    int t = threadIdx.x;
    int warp = t >> 5, lane = t & 31;
    int b = blockIdx.x;
    if (b < 128) {
        bool do_u = (b < 64);
        int row = (do_u ? b : b - 64) * 8 + warp;
        const float* W   = do_u ? Qw : Kw;
        const float* vec = do_u ? Kb : Qb;
        const float* wr = W + (size_t)row * F;
        float s = 0.0f;
#pragma unroll 4
        for (int k = lane; k < F; k += 32) s += wr[k] * vec[k];
#pragma unroll
        for (int o = 16; o > 0; o >>= 1) s += __shfl_xor_sync(0xFFFFFFFFu, s, o);
        if (lane == 0) (do_u ? g_u : g_v)[row] = s;
    } else {
        __shared__ float red[256];
        float s = Qb[t] * Kb[t] + Qb[t + 256] * Kb[t + 256];
        red[t] = s;
        __syncthreads();
        for (int o = 128; o > 0; o >>= 1) {
            if (t < o) red[t] += red[t + o];
            __syncthreads();
        }
        if (t == 0) g_c = red[0];
    }
}

// ---------------- 3. h = relu(adj@XW + b), fused b_j = h_j.v -----------------
__global__ __launch_bounds__(128) void spmm_relu_bvec(const float* __restrict__ XW,
                                                      const float* __restrict__ bias,
                                                      float* __restrict__ H) {
    __shared__ float red[128];
    int row = blockIdx.x, t = threadIdx.x;
    int len = g_len[row];
    const int* cols = g_col + row * ELLW;
    float4 a0 = make_float4(0, 0, 0, 0), a1 = make_float4(0, 0, 0, 0);
    float4 a2 = make_float4(0, 0, 0, 0), a3 = make_float4(0, 0, 0, 0);
    int e = 0;
    for (; e + 3 < len; e += 4) {
        int j0 = __ldg(cols + e),     j1 = __ldg(cols + e + 1);
        int j2 = __ldg(cols + e + 2), j3 = __ldg(cols + e + 3);
        float4 v0 = *(const float4*)(XW + (size_t)j0 * F + (t << 2));
        float4 v1 = *(const float4*)(XW + (size_t)j1 * F + (t << 2));
        float4 v2 = *(const float4*)(XW + (size_t)j2 * F + (t << 2));
        float4 v3 = *(const float4*)(XW + (size_t)j3 * F + (t << 2));
        a0.x += v0.x; a0.y += v0.y; a0.z += v0.z; a0.w += v0.w;
        a1.x += v1.x; a1.y += v1.y; a1.z += v1.z; a1.w += v1.w;
        a2.x += v2.x; a2.y += v2.y; a2.z += v2.z; a2.w += v2.w;
        a3.x += v3.x; a3.y += v3.y; a3.z += v3.z; a3.w += v3.w;
    }
    for (; e < len; e++) {
        int j0 = __ldg(cols + e);
        float4 v0 = *(const float4*)(XW + (size_t)j0 * F + (t << 2));
        a0.x += v0.x; a0.y += v0.y; a0.z += v0.z; a0.w += v0.w;
    }
    float4 b4 = *(const float4*)(bias + (t << 2));
    float4 o;
    o.x = fmaxf((a0.x + a1.x) + (a2.x + a3.x) + b4.x, 0.0f);
    o.y = fmaxf((a0.y + a1.y) + (a2.y + a3.y) + b4.y, 0.0f);
    o.z = fmaxf((a0.z + a1.z) + (a2.z + a3.z) + b4.z, 0.0f);
    o.w = fmaxf((a0.w + a1.w) + (a2.w + a3.w) + b4.w, 0.0f);
    *(float4*)(H + (size_t)row * F + (t << 2)) = o;

    // fused: b_row = h_row . v
    float4 v4 = ((const float4*)g_v)[t];
    red[t] = o.x * v4.x + o.y * v4.y + o.z * v4.z + o.w * v4.w;
    __syncthreads();
    for (int s = 64; s > 0; s >>= 1) {
        if (t < s) red[t] += red[t + s];
        __syncthreads();
    }
    if (t == 0) g_bv[row] = red[0];
}

// ---------------- 4. edge scores + masked softmax ----------------------------
__global__ __launch_bounds__(256) void scores_softmax(const float* __restrict__ H,
                                                      const float* __restrict__ R) {
    __shared__ float4 qs[128];
    __shared__ float sc[ELLW];
    __shared__ float red[256];
    __shared__ float sA;
    int row = blockIdx.x, t = threadIdx.x;
    if (t < 128) qs[t] = *(const float4*)(H + (size_t)row * F + (t << 2));
    __syncthreads();

    float ap = 0.0f;
    if (t < 128) {
        float4 q = qs[t];
        float4 uu = ((const float4*)g_u)[t];
        ap = q.x * uu.x + q.y * uu.y + q.z * uu.z + q.w * uu.w;
    }
    red[t] = ap;
    __syncthreads();
    for (int s = 128; s > 0; s >>= 1) {
        if (t < s) red[t] += red[t + s];
        __syncthreads();
    }
    if (t == 0) sA = red[0] + g_c;
    __syncthreads();
    float abase = sA;

    int len = g_len[row];
    int lane = t & 31, w = t >> 5;
    const int* cols = g_col + row * ELLW;
    for (int e = w; e < len; e += 8) {
        int j = __ldg(cols + e);
        const float4* kr = (const float4*)(R + (size_t)j * F);
        float s = 0.0f;
#pragma unroll
        for (int q = 0; q < 4; q++) {
            float4 kv = kr[lane + 32 * q];
            float4 qv = qs[lane + 32 * q];
            s += kv.x * qv.x + kv.y * qv.y + kv.z * qv.z + kv.w * qv.w;
        }
#pragma unroll
        for (int o = 16; o > 0; o >>= 1) s += __shfl_xor_sync(0xFFFFFFFFu, s, o);
        if (lane == 0) sc[e] = s + abase + g_bv[j];
    }
    __syncthreads();

    red[t] = (t < len) ? sc[t] : -INFINITY;
    __syncthreads();
    for (int s = 128; s > 0; s >>= 1) {
        if (t < s) red[t] = fmaxf(red[t], red[t + s]);
        __syncthreads();
    }
    float m = fmaxf(red[0], 0.0f);
    __syncthreads();

    float ez = (t < len) ? expf(sc[t] - m) : 0.0f;
    red[t] = ez;
    __syncthreads();
    for (int s = 128; s > 0; s >>= 1) {
        if (t < s) red[t] += red[t + s];
        __syncthreads();
    }
    float em = expf(-m);
    float Z = red[0] + (float)(NROWS - len) * em;
    float w0 = em / Z;
    if (t < len) g_w[row * ELLW + t] = ez / Z - w0;
    if (t == 0) g_w0[row] = w0;
}

// ---------------- 5. column sums of Vh ---------------------------------------
__global__ __launch_bounds__(512) void colsum_part(const float* __restrict__ V) {
    int b = blockIdx.x, c = threadIdx.x;
    const float* base = V + (size_t)b * 256 * F + c;
    float s0 = 0, s1 = 0, s2 = 0, s3 = 0;
#pragma unroll 4
    for (int r = 0; r < 256; r += 4) {
        s0 += base[(size_t)(r + 0) * F];
        s1 += base[(size_t)(r + 1) * F];
        s2 += base[(size_t)(r + 2) * F];
        s3 += base[(size_t)(r + 3) * F];
    }
    g_part[b * F + c] = (s0 + s1) + (s2 + s3);
}
__global__ __launch_bounds__(512) void colsum_final() {
    int c = threadIdx.x;
    float s = 0.0f;
#pragma unroll
    for (int b = 0; b < 32; b++) s += g_part[b * F + c];
    g_csum[c] = s;
}

// ---------------- 6. X_tilde = attention @ Vh, fused LayerNorm ---------------
__global__ __launch_bounds__(128) void xt_layernorm(const float* __restrict__ V,
                                                    const float* __restrict__ lng,
                                                    const float* __restrict__ lnb,
                                                    float* __restrict__ Xt) {
    __shared__ float red[128];
    int row = blockIdx.x, t = threadIdx.x;
    int len = g_len[row];
    float w0 = g_w0[row];
    const int* cols = g_col + row * ELLW;
    const float* wts = g_w + row * ELLW;

    float4 cs = ((const float4*)g_csum)[t];
    float4 a0 = make_float4(w0 * cs.x, w0 * cs.y, w0 * cs.z, w0 * cs.w);
    float4 a1 = make_float4(0, 0, 0, 0);
    float4 a2 = make_float4(0, 0, 0, 0);
    float4 a3 = make_float4(0, 0, 0, 0);
    int e = 0;
    for (; e + 3 < len; e += 4) {
        int j0 = __ldg(cols + e),     j1 = __ldg(cols + e + 1);
        int j2 = __ldg(cols + e + 2), j3 = __ldg(cols + e + 3);
        float w_0 = __ldg(wts + e),     w_1 = __ldg(wts + e + 1);
        float w_2 = __ldg(wts + e + 2), w_3 = __ldg(wts + e + 3);
        float4 v0 = *(const float4*)(V + (size_t)j0 * F + (t << 2));
        float4 v1 = *(const float4*)(V + (size_t)j1 * F + (t << 2));
        float4 v2 = *(const float4*)(V + (size_t)j2 * F + (t << 2));
        float4 v3 = *(const float4*)(V + (size_t)j3 * F + (t << 2));
        a0.x += w_0 * v0.x; a0.y += w_0 * v0.y; a0.z += w_0 * v0.z; a0.w += w_0 * v0.w;
        a1.x += w_1 * v1.x; a1.y += w_1 * v1.y; a1.z += w_1 * v1.z; a1.w += w_1 * v1.w;
        a2.x += w_2 * v2.x; a2.y += w_2 * v2.y; a2.z += w_2 * v2.z; a2.w += w_2 * v2.w;
        a3.x += w_3 * v3.x; a3.y += w_3 * v3.y; a3.z += w_3 * v3.z; a3.w += w_3 * v3.w;
    }
    for (; e < len; e++) {
        int j0 = __ldg(cols + e);
        float w_0 = __ldg(wts + e);
        float4 v0 = *(const float4*)(V + (size_t)j0 * F + (t << 2));
        a0.x += w_0 * v0.x; a0.y += w_0 * v0.y; a0.z += w_0 * v0.z; a0.w += w_0 * v0.w;
    }
    float4 x;
    x.x = (a0.x + a1.x) + (a2.x + a3.x);
    x.y = (a0.y + a1.y) + (a2.y + a3.y);
    x.z = (a0.z + a1.z) + (a2.z + a3.z);
    x.w = (a0.w + a1.w) + (a2.w + a3.w);

    red[t] = x.x + x.y + x.z + x.w;
    __syncthreads();
    for (int s = 64; s > 0; s >>= 1) {
        if (t < s) red[t] += red[t + s];
        __syncthreads();
    }
    float mu = red[0] * (1.0f / F);
    __syncthreads();
    float dx = x.x - mu, dy = x.y - mu, dz = x.z - mu, dw = x.w - mu;
    red[t] = dx * dx + dy * dy + dz * dz + dw * dw;
    __syncthreads();
    for (int s = 64; s > 0; s >>= 1) {
        if (t < s) red[t] += red[t + s];
        __syncthreads();
    }
    float inv = rsqrtf(red[0] * (1.0f / F) + 1e-5f);

    float4 g4 = *(const float4*)(lng + (t << 2));
    float4 b4 = *(const float4*)(lnb + (t << 2));
    float4 o;
    o.x = dx * inv * g4.x + b4.x;
    o.y = dy * inv * g4.y + b4.y;
    o.z = dz * inv * g4.z + b4.z;
    o.w = dw * inv * g4.w + b4.w;
    *(float4*)(Xt + (size_t)row * F + (t << 2)) = o;
}

// ---------------- 7. Y = Xt @ gcn2_W -----------------------------------------
__global__ __launch_bounds__(256) void ygemm(const float* __restrict__ Xt,
                                             const float* __restrict__ W2,
                                             float* __restrict__ Y) {
    __shared__ float w2t[NCLS * F];
    int t = threadIdx.x;
    for (int i = t; i < NCLS * F; i += 256) {
        int c = i / F, k = i - c * F;
        w2t[i] = W2[k * NCLS + c];
    }
    __syncthreads();
    int warp = t >> 5, lane = t & 31;
    int row = blockIdx.x * 8 + warp;
    float p[NCLS];
#pragma unroll
    for (int c = 0; c < NCLS; c++) p[c] = 0.0f;
    const float* xr = Xt + (size_t)row * F;
    for (int k = lane; k < F; k += 32) {
        float xv = xr[k];
#pragma unroll
        for (int c = 0; c < NCLS; c++) p[c] += xv * w2t[c * F + k];
    }
#pragma unroll
    for (int c = 0; c < NCLS; c++) {
#pragma unroll
        for (int o = 16; o > 0; o >>= 1) p[c] += __shfl_xor_sync(0xFFFFFFFFu, p[c], o);
    }
    if (lane == 0) {
#pragma unroll
        for (int c = 0; c < NCLS; c++) Y[row * NCLS + c] = p[c];
    }
}

// ---------------- 8. z = adj @ Y + b2, row softmax ---------------------------
__global__ __launch_bounds__(256) void z_softmax(const float* __restrict__ Y,
                                                 const float* __restrict__ b2,
                                                 float* __restrict__ out) {
    int t = threadIdx.x;
    int row = blockIdx.x * 32 + (t >> 3);
    int c = t & 7;
    int len = g_len[row];
    const int* cols = g_col + row * ELLW;
    float acc = b2[c];
    for (int e = 0; e < len; e++) acc += __ldg(Y + __ldg(cols + e) * NCLS + c);
    float m = acc;
#pragma unroll
    for (int o = 4; o > 0; o >>= 1) m = fmaxf(m, __shfl_xor_sync(0xFFFFFFFFu, m, o));
    float ez = expf(acc - m);
    float s = ez;
#pragma unroll
    for (int o = 4; o > 0; o >>= 1) s += __shfl_xor_sync(0xFFFFFFFFu, s, o);
    out[row * NCLS + c] = ez / s;
}

// ---------------- launcher: priority-based fork-join overlap -----------------
extern "C" void kernel_launch(void* const* d_in, const int* in_sizes, int n_in,
                              void* d_out, int out_size) {
    const float* adj    = (const float*)d_in[0];
    const float* x      = (const float*)d_in[1];
    const float* gcn1_W = (const float*)d_in[2];
    const float* gcn1_b = (const float*)d_in[3];
    const float* Qw     = (const float*)d_in[4];
    const float* Qb     = (const float*)d_in[5];
    const float* Kw     = (const float*)d_in[6];
    const float* Kb     = (const float*)d_in[7];
    const float* Vw     = (const float*)d_in[8];
    const float* Vb     = (const float*)d_in[9];
    const float* ln_g   = (const float*)d_in[10];
    const float* ln_b   = (const float*)d_in[11];
    const float* gcn2_W = (const float*)d_in[12];
    const float* gcn2_b = (const float*)d_in[13];
    float* out = (float*)d_out;

    float *XW, *H, *R, *V, *Xt, *Y, *N;
    cudaGetSymbolAddress((void**)&XW, g_XW);
    cudaGetSymbolAddress((void**)&H,  g_h);
    cudaGetSymbolAddress((void**)&R,  g_R);
    cudaGetSymbolAddress((void**)&V,  g_V);
    cudaGetSymbolAddress((void**)&Xt, g_Xt);
    cudaGetSymbolAddress((void**)&Y,  g_Y);
    cudaGetSymbolAddress((void**)&N,  g_N);

    static cudaStream_t s1 = nullptr;
    static cudaEvent_t evFork = nullptr, evPrep = nullptr, evR = nullptr, evSc = nullptr;
    if (!s1) {
        int loPri = 0, hiPri = 0;
        cudaDeviceGetStreamPriorityRange(&loPri, &hiPri);
        // s1 = LOWEST priority: its big-grid kernels backfill instead of
        // monopolizing the work distributor, letting stream-0 grids co-run.
        cudaStreamCreateWithPriority(&s1, cudaStreamNonBlocking, loPri);
        cudaEventCreateWithFlags(&evFork, cudaEventDisableTiming);
        cudaEventCreateWithFlags(&evPrep, cudaEventDisableTiming);
        cudaEventCreateWithFlags(&evR,    cudaEventDisableTiming);
        cudaEventCreateWithFlags(&evSc,   cudaEventDisableTiming);
    }

    dim3 gg(F / 128, NROWS / 128);

    // fork: s1 branches off stream 0
    cudaEventRecord(evFork, 0);
    cudaStreamWaitEvent(s1, evFork, 0);

    // stream 0: adjacency scan (HBM-bound)
    build_ell<<<NROWS / 4, 128, 0, 0>>>(adj);
    // stream 1 (low prio): x@W1 GEMM (FMA-bound) + score-prep algebra
    sgemm512<<<gg, 256, 0, s1>>>(x, gcn1_W, nullptr, XW);
    gemm_abt512<<<dim3(8, 8), 256, 0, s1>>>(Kw, Qw, N);   // N = Kw @ Qw^T
    uvc_kernel<<<129, 256, 0, s1>>>(Qw, Qb, Kw, Kb);
    cudaEventRecord(evPrep, s1);
    cudaStreamWaitEvent(0, evPrep, 0);

    // join: needs ELL + XW + v
    spmm_relu_bvec<<<NROWS, 128, 0, 0>>>(XW, gcn1_b, H);

    // R on stream 0; then scores (low-prio s1, 8192 CTAs backfill) overlaps
    // the V-GEMM + colsum running at default priority on stream 0.
    sgemm512<<<gg, 256, 0, 0>>>(H, N, nullptr, R);
    cudaEventRecord(evR, 0);
    cudaStreamWaitEvent(s1, evR, 0);
    scores_softmax<<<NROWS, 256, 0, s1>>>(H, R);          // low prio: backfills
    sgemm512<<<gg, 256, 0, 0>>>(H, Vw, Vb, V);            // priority: gets slots
    colsum_part<<<32, 512, 0, 0>>>(V);
    colsum_final<<<1, 512, 0, 0>>>();
    cudaEventRecord(evSc, s1);
    cudaStreamWaitEvent(0, evSc, 0);

    // join: needs weights (scores) + V + colsum
    xt_layernorm<<<NROWS, 128, 0, 0>>>(V, ln_g, ln_b, Xt);
    ygemm<<<NROWS / 8, 256, 0, 0>>>(Xt, gcn2_W, Y);
    z_softmax<<<NROWS / 32, 256, 0, 0>>>(Y, gcn2_b, out);
}

// round 16
// speedup vs baseline: 1.5284x; 1.0913x over previous
#include <cuda_runtime.h>
#include <math.h>

#define NROWS 8192
#define F     512
#define NCLS  8
#define ELLW  192

// ---------------- static scratch (device globals; no runtime alloc) ----------
__device__ __align__(16) float g_XW[NROWS * F];   // x@W1 ; later reused as Xpre
__device__ __align__(16) float g_h [NROWS * F];
__device__ __align__(16) float g_R [NROWS * F];   // R' = h @ M
__device__ __align__(16) float g_V [NROWS * F];   // T = Xpre@Vw + Vb
__device__ __align__(16) float g_Xt[NROWS * F];
__device__ __align__(16) float g_Y [NROWS * NCLS];
__device__ __align__(16) float g_N [F * F];       // M = Qw @ Kw^T
__device__ __align__(16) float g_u [F];           // u = Qw @ Kb
__device__ __align__(16) float g_v [F];           // v = Kw @ Qb
__device__ float g_c;                             // c = Qb . Kb
__device__ float g_bv[NROWS];                     // b_j = h_j . v
__device__ float g_av[NROWS];                     // a_i = h_i . u
__device__ int   g_col[NROWS * ELLW];
__device__ int   g_len[NROWS];
__device__ __align__(16) float g_csum[F];         // column sums of h
__device__ float g_part[32 * F];

// ---------------- packed f32x2 helpers (Blackwell FFMA2 path) ----------------
__device__ __forceinline__ unsigned long long pk2(float x, float y) {
    unsigned long long r;
    asm("mov.b64 %0, {%1, %2};" : "=l"(r) : "f"(x), "f"(y));
    return r;
}
__device__ __forceinline__ float2 upk2(unsigned long long v) {
    float2 r;
    asm("mov.b64 {%0, %1}, %2;" : "=f"(r.x), "=f"(r.y) : "l"(v));
    return r;
}
__device__ __forceinline__ void fma2(unsigned long long& d,
                                     unsigned long long a,
                                     unsigned long long b) {
    asm("fma.rn.f32x2 %0, %1, %2, %0;" : "+l"(d) : "l"(a), "l"(b));
}

// ---------------- 1. adjacency -> ELL (warp/row, MLP=4, ballot compaction) ---
__global__ __launch_bounds__(128) void build_ell(const float* __restrict__ adj) {
    int warp_id = blockIdx.x * (blockDim.x >> 5) + (threadIdx.x >> 5);
    if (warp_id >= NROWS) return;
    int lane = threadIdx.x & 31;
    const float* ar = adj + (size_t)warp_id * NROWS;
    int cnt = 0;
    int* crow = g_col + warp_id * ELLW;
    for (int b = 0; b < NROWS; b += 128) {
        float v0 = ar[b + lane];
        float v1 = ar[b + 32 + lane];
        float v2 = ar[b + 64 + lane];
        float v3 = ar[b + 96 + lane];
        unsigned m0 = __ballot_sync(0xFFFFFFFFu, v0 != 0.0f);
        unsigned m1 = __ballot_sync(0xFFFFFFFFu, v1 != 0.0f);
        unsigned m2 = __ballot_sync(0xFFFFFFFFu, v2 != 0.0f);
        unsigned m3 = __ballot_sync(0xFFFFFFFFu, v3 != 0.0f);
        unsigned lm = (1u << lane) - 1u;
        if (v0 != 0.0f) { int p = cnt + __popc(m0 & lm); if (p < ELLW) crow[p] = b + lane; }
        cnt += __popc(m0);
        if (v1 != 0.0f) { int p = cnt + __popc(m1 & lm); if (p < ELLW) crow[p] = b + 32 + lane; }
        cnt += __popc(m1);
        if (v2 != 0.0f) { int p = cnt + __popc(m2 & lm); if (p < ELLW) crow[p] = b + 64 + lane; }
        cnt += __popc(m2);
        if (v3 != 0.0f) { int p = cnt + __popc(m3 & lm); if (p < ELLW) crow[p] = b + 96 + lane; }
        cnt += __popc(m3);
    }
    if (lane == 0) g_len[warp_id] = cnt < ELLW ? cnt : ELLW;
}

// ---------------- 2. fp32 SGEMM with packed FFMA2 (champion) -----------------
__global__ __launch_bounds__(256, 2) void sgemm512(const float* __restrict__ A,
                                                   const float* __restrict__ B,
                                                   const float* __restrict__ bias,
                                                   float* __restrict__ C) {
    __shared__ float As[2][16][132];
    __shared__ float Bs[2][16][128];
    const int tid = threadIdx.x;
    const int bm = blockIdx.y, bn = blockIdx.x;
    const float* Ab = A + (size_t)bm * 128 * F;
    const float* Bb = B + bn * 128;

    const int arow = tid >> 2, acol = (tid & 3) << 2;
    const int brow = tid >> 5, bcol = (tid & 31) << 2;
    const int tx = tid & 15, ty = tid >> 4;

    float4 pa0, pa1, pb0, pb1;
    pa0 = *(const float4*)(Ab + (size_t)arow * F + acol);
    pa1 = *(const float4*)(Ab + (size_t)(arow + 64) * F + acol);
    pb0 = *(const float4*)(Bb + (size_t)brow * F + bcol);
    pb1 = *(const float4*)(Bb + (size_t)(brow + 8) * F + bcol);

    unsigned long long acc[4][8];
#pragma unroll
    for (int ip = 0; ip < 4; ip++)
#pragma unroll
        for (int j = 0; j < 8; j++) acc[ip][j] = 0ULL;

    As[0][acol + 0][arow] = pa0.x; As[0][acol + 1][arow] = pa0.y;
    As[0][acol + 2][arow] = pa0.z; As[0][acol + 3][arow] = pa0.w;
    As[0][acol + 0][arow + 64] = pa1.x; As[0][acol + 1][arow + 64] = pa1.y;
    As[0][acol + 2][arow + 64] = pa1.z; As[0][acol + 3][arow + 64] = pa1.w;
    *(float4*)(&Bs[0][brow][bcol])     = pb0;
    *(float4*)(&Bs[0][brow + 8][bcol]) = pb1;
    __syncthreads();

    int buf = 0;
#pragma unroll 1
    for (int kt = 16; kt <= F; kt += 16) {
        if (kt < F) {
            pa0 = *(const float4*)(Ab + (size_t)arow * F + kt + acol);
            pa1 = *(const float4*)(Ab + (size_t)(arow + 64) * F + kt + acol);
            pb0 = *(const float4*)(Bb + (size_t)(kt + brow) * F + bcol);
            pb1 = *(const float4*)(Bb + (size_t)(kt + brow + 8) * F + bcol);
        }
#pragma unroll
        for (int k = 0; k < 16; k++) {
            float4 av0 = *(const float4*)(&As[buf][k][ty * 4]);
            float4 av1 = *(const float4*)(&As[buf][k][64 + ty * 4]);
            float4 bv0 = *(const float4*)(&Bs[buf][k][tx * 4]);
            float4 bv1 = *(const float4*)(&Bs[buf][k][64 + tx * 4]);
            unsigned long long ap[4], bd[8];
            ap[0] = pk2(av0.x, av0.y); ap[1] = pk2(av0.z, av0.w);
            ap[2] = pk2(av1.x, av1.y); ap[3] = pk2(av1.z, av1.w);
            bd[0] = pk2(bv0.x, bv0.x); bd[1] = pk2(bv0.y, bv0.y);
            bd[2] = pk2(bv0.z, bv0.z); bd[3] = pk2(bv0.w, bv0.w);
            bd[4] = pk2(bv1.x, bv1.x); bd[5] = pk2(bv1.y, bv1.y);
            bd[6] = pk2(bv1.z, bv1.z); bd[7] = pk2(bv1.w, bv1.w);
#pragma unroll
            for (int ip = 0; ip < 4; ip++)
#pragma unroll
                for (int j = 0; j < 8; j++) fma2(acc[ip][j], ap[ip], bd[j]);
        }
        if (kt < F) {
            int nb = buf ^ 1;
            As[nb][acol + 0][arow] = pa0.x; As[nb][acol + 1][arow] = pa0.y;
            As[nb][acol + 2][arow] = pa0.z; As[nb][acol + 3][arow] = pa0.w;
            As[nb][acol + 0][arow + 64] = pa1.x; As[nb][acol + 1][arow + 64] = pa1.y;
            As[nb][acol + 2][arow + 64] = pa1.z; As[nb][acol + 3][arow + 64] = pa1.w;
            *(float4*)(&Bs[nb][brow][bcol])     = pb0;
            *(float4*)(&Bs[nb][brow + 8][bcol]) = pb1;
            __syncthreads();
            buf = nb;
        }
    }

    float bb[8];
#pragma unroll
    for (int j = 0; j < 4; j++) {
        bb[j]     = bias ? bias[bn * 128 + tx * 4 + j]      : 0.0f;
        bb[4 + j] = bias ? bias[bn * 128 + 64 + tx * 4 + j] : 0.0f;
    }
#pragma unroll
    for (int ip = 0; ip < 4; ip++) {
        int rbase = (ip < 2) ? (ty * 4 + 2 * ip) : (64 + ty * 4 + 2 * (ip - 2));
        float2 c[8];
#pragma unroll
        for (int j = 0; j < 8; j++) c[j] = upk2(acc[ip][j]);
        {
            int row = bm * 128 + rbase;
            float* Cr = C + (size_t)row * F + bn * 128;
            float4 v0 = make_float4(c[0].x + bb[0], c[1].x + bb[1],
                                    c[2].x + bb[2], c[3].x + bb[3]);
            float4 v1 = make_float4(c[4].x + bb[4], c[5].x + bb[5],
                                    c[6].x + bb[6], c[7].x + bb[7]);
            *(float4*)(Cr + tx * 4)      = v0;
            *(float4*)(Cr + 64 + tx * 4) = v1;
        }
        {
            int row = bm * 128 + rbase + 1;
            float* Cr = C + (size_t)row * F + bn * 128;
            float4 v0 = make_float4(c[0].y + bb[0], c[1].y + bb[1],
                                    c[2].y + bb[2], c[3].y + bb[3]);
            float4 v1 = make_float4(c[4].y + bb[4], c[5].y + bb[5],
                                    c[6].y + bb[6], c[7].y + bb[7]);
            *(float4*)(Cr + tx * 4)      = v0;
            *(float4*)(Cr + 64 + tx * 4) = v1;
        }
    }
}

// ---------------- 2b. M = Qw @ Kw^T ------------------------------------------
__global__ __launch_bounds__(256) void gemm_abt512(const float* __restrict__ A,
                                                   const float* __restrict__ B,
                                                   float* __restrict__ C) {
    __shared__ float As[64][33];
    __shared__ float Bs[64][33];
    const int t = threadIdx.x;
    const int tx = t & 15, ty = t >> 4;
    const int m0 = blockIdx.y * 64, n0 = blockIdx.x * 64;
    float acc[4][4];
#pragma unroll
    for (int i = 0; i < 4; i++)
#pragma unroll
        for (int j = 0; j < 4; j++) acc[i][j] = 0.0f;

    for (int kt = 0; kt < F; kt += 32) {
#pragma unroll
        for (int r = 0; r < 8; r++) {
            int idx = t + r * 256;
            int row = idx >> 5, k = idx & 31;
            As[row][k] = A[(size_t)(m0 + row) * F + kt + k];
            Bs[row][k] = B[(size_t)(n0 + row) * F + kt + k];
        }
        __syncthreads();
#pragma unroll
        for (int k = 0; k < 32; k++) {
            float a[4], b[4];
#pragma unroll
            for (int i = 0; i < 4; i++) a[i] = As[ty * 4 + i][k];
#pragma unroll
            for (int j = 0; j < 4; j++) b[j] = Bs[tx * 4 + j][k];
#pragma unroll
            for (int i = 0; i < 4; i++)
#pragma unroll
                for (int j = 0; j < 4; j++) acc[i][j] = fmaf(a[i], b[j], acc[i][j]);
        }
        __syncthreads();
    }
#pragma unroll
    for (int i = 0; i < 4; i++)
#pragma unroll
        for (int j = 0; j < 4; j++)
            C[(size_t)(m0 + ty * 4 + i) * F + n0 + tx * 4 + j] = acc[i][j];
}

// ---------------- 2c. u = Qw@Kb, v = Kw@Qb, c = Qb.Kb (warp per row) ---------
__global__ __launch_bounds__(256) void uvc_kernel(const float* __restrict__ Qw,
                                                  const float* __restrict__ Qb,
                                                  const float* __restrict__ Kw,
                                                  const float* __restrict__ Kb) {
    int t = threadIdx.x;
    int warp = t >> 5, lane = t & 31;
    int b = blockIdx.x;
    if (b < 128) {
        bool do_u = (b < 64);
        int row = (do_u ? b : b - 64) * 8 + warp;
        const float* W   = do_u ? Qw : Kw;
        const float* vec = do_u ? Kb : Qb;
        const float* wr = W + (size_t)row * F;
        float s = 0.0f;
#pragma unroll 4
        for (int k = lane; k < F; k += 32) s += wr[k] * vec[k];
#pragma unroll
        for (int o = 16; o > 0; o >>= 1) s += __shfl_xor_sync(0xFFFFFFFFu, s, o);
        if (lane == 0) (do_u ? g_u : g_v)[row] = s;
    } else {
        __shared__ float red[256];
        float s = Qb[t] * Kb[t] + Qb[t + 256] * Kb[t + 256];
        red[t] = s;
        __syncthreads();
        for (int o = 128; o > 0; o >>= 1) {
            if (t < o) red[t] += red[t + o];
            __syncthreads();
        }
        if (t == 0) g_c = red[0];
    }
}

// ---------------- 3. h = relu(adj@XW + b), fused a_i=h.u, b_i=h.v ------------
__global__ __launch_bounds__(128) void spmm_relu_bav(const float* __restrict__ XW,
                                                     const float* __restrict__ bias,
                                                     float* __restrict__ H) {
    __shared__ float red[128];
    int row = blockIdx.x, t = threadIdx.x;
    int len = g_len[row];
    const int* cols = g_col + row * ELLW;
    float4 a0 = make_float4(0, 0, 0, 0), a1 = make_float4(0, 0, 0, 0);
    float4 a2 = make_float4(0, 0, 0, 0), a3 = make_float4(0, 0, 0, 0);
    int e = 0;
    for (; e + 3 < len; e += 4) {
        int j0 = __ldg(cols + e),     j1 = __ldg(cols + e + 1);
        int j2 = __ldg(cols + e + 2), j3 = __ldg(cols + e + 3);
        float4 v0 = *(const float4*)(XW + (size_t)j0 * F + (t << 2));
        float4 v1 = *(const float4*)(XW + (size_t)j1 * F + (t << 2));
        float4 v2 = *(const float4*)(XW + (size_t)j2 * F + (t << 2));
        float4 v3 = *(const float4*)(XW + (size_t)j3 * F + (t << 2));
        a0.x += v0.x; a0.y += v0.y; a0.z += v0.z; a0.w += v0.w;
        a1.x += v1.x; a1.y += v1.y; a1.z += v1.z; a1.w += v1.w;
        a2.x += v2.x; a2.y += v2.y; a2.z += v2.z; a2.w += v2.w;
        a3.x += v3.x; a3.y += v3.y; a3.z += v3.z; a3.w += v3.w;
    }
    for (; e < len; e++) {
        int j0 = __ldg(cols + e);
        float4 v0 = *(const float4*)(XW + (size_t)j0 * F + (t << 2));
        a0.x += v0.x; a0.y += v0.y; a0.z += v0.z; a0.w += v0.w;
    }
    float4 b4 = *(const float4*)(bias + (t << 2));
    float4 o;
    o.x = fmaxf((a0.x + a1.x) + (a2.x + a3.x) + b4.x, 0.0f);
    o.y = fmaxf((a0.y + a1.y) + (a2.y + a3.y) + b4.y, 0.0f);
    o.z = fmaxf((a0.z + a1.z) + (a2.z + a3.z) + b4.z, 0.0f);
    o.w = fmaxf((a0.w + a1.w) + (a2.w + a3.w) + b4.w, 0.0f);
    *(float4*)(H + (size_t)row * F + (t << 2)) = o;

    // fused: b_row = h_row . v
    float4 v4 = ((const float4*)g_v)[t];
    red[t] = o.x * v4.x + o.y * v4.y + o.z * v4.z + o.w * v4.w;
    __syncthreads();
    for (int s = 64; s > 0; s >>= 1) {
        if (t < s) red[t] += red[t + s];
        __syncthreads();
    }
    if (t == 0) g_bv[row] = red[0];
    __syncthreads();
    // fused: a_row = h_row . u
    float4 u4 = ((const float4*)g_u)[t];
    red[t] = o.x * u4.x + o.y * u4.y + o.z * u4.z + o.w * u4.w;
    __syncthreads();
    for (int s = 64; s > 0; s >>= 1) {
        if (t < s) red[t] += red[t + s];
        __syncthreads();
    }
    if (t == 0) g_av[row] = red[0];
}

// ---------------- 4. column sums of h ----------------------------------------
__global__ __launch_bounds__(512) void colsum_part(const float* __restrict__ X) {
    int b = blockIdx.x, c = threadIdx.x;
    const float* base = X + (size_t)b * 256 * F + c;
    float s0 = 0, s1 = 0, s2 = 0, s3 = 0;
#pragma unroll 4
    for (int r = 0; r < 256; r += 4) {
        s0 += base[(size_t)(r + 0) * F];
        s1 += base[(size_t)(r + 1) * F];
        s2 += base[(size_t)(r + 2) * F];
        s3 += base[(size_t)(r + 3) * F];
    }
    g_part[b * F + c] = (s0 + s1) + (s2 + s3);
}
__global__ __launch_bounds__(512) void colsum_final() {
    int c = threadIdx.x;
    float s = 0.0f;
#pragma unroll
    for (int b = 0; b < 32; b++) s += g_part[b * F + c];
    g_csum[c] = s;
}

// ---------------- 5. fused attention: Xpre = softmax(adj*(QK)) @ h -----------
// s_ij = R'_i . h_j + a_i + b_j + c ; online softmax per warp, flash merge.
// Single gather of h per edge serves both score and aggregation.
__global__ __launch_bounds__(128) void attn_fused(const float* __restrict__ H,
                                                  const float* __restrict__ Rp,
                                                  float* __restrict__ Xp) {
    __shared__ float4 rs[128];
    __shared__ float4 mG[4][128];
    __shared__ float4 mS[4][128];
    __shared__ float wm[4], wh[4];
    int row = blockIdx.x, t = threadIdx.x, lane = t & 31, w = t >> 5;
    rs[t] = ((const float4*)(Rp + (size_t)row * F))[t];
    __syncthreads();

    int len = g_len[row];
    const int* cols = g_col + row * ELLW;
    float abase = g_av[row] + g_c;

    float4 Gm[4], Sh[4];
#pragma unroll
    for (int q = 0; q < 4; q++) {
        Gm[q] = make_float4(0, 0, 0, 0);
        Sh[q] = make_float4(0, 0, 0, 0);
    }
    float m_w = -INFINITY, Hm = 0.0f;

    for (int e = w; e < len; e += 4) {
        int j = __ldg(cols + e);
        const float4* hj = (const float4*)(H + (size_t)j * F);
        float4 hv[4];
#pragma unroll
        for (int q = 0; q < 4; q++) hv[q] = hj[lane + 32 * q];
        float s = 0.0f;
#pragma unroll
        for (int q = 0; q < 4; q++) {
            float4 rv = rs[lane + 32 * q];
            s += hv[q].x * rv.x + hv[q].y * rv.y + hv[q].z * rv.z + hv[q].w * rv.w;
        }
#pragma unroll
        for (int o = 16; o > 0; o >>= 1) s += __shfl_xor_sync(0xFFFFFFFFu, s, o);
        s += abase + __ldg(g_bv + j);

        if (s > m_w) {
            float sc = (m_w == -INFINITY) ? 0.0f : expf(m_w - s);
#pragma unroll
            for (int q = 0; q < 4; q++) {
                Gm[q].x *= sc; Gm[q].y *= sc; Gm[q].z *= sc; Gm[q].w *= sc;
            }
            Hm *= sc;
            m_w = s;
        }
        float we = expf(s - m_w);
        Hm += we;
#pragma unroll
        for (int q = 0; q < 4; q++) {
            Gm[q].x += we * hv[q].x; Gm[q].y += we * hv[q].y;
            Gm[q].z += we * hv[q].z; Gm[q].w += we * hv[q].w;
            Sh[q].x += hv[q].x; Sh[q].y += hv[q].y;
            Sh[q].z += hv[q].z; Sh[q].w += hv[q].w;
        }
    }

    if (lane == 0) { wm[w] = m_w; wh[w] = Hm; }
#pragma unroll
    for (int q = 0; q < 4; q++) {
        mG[w][lane + 32 * q] = Gm[q];
        mS[w][lane + 32 * q] = Sh[q];
    }
    __syncthreads();

    // merge: M includes the 0 baseline of the N-len zero-score entries
    float M = 0.0f;
#pragma unroll
    for (int ww = 0; ww < 4; ww++) M = fmaxf(M, wm[ww]);
    float em = expf(-M);
    float Z = (float)(NROWS - len) * em;
#pragma unroll
    for (int ww = 0; ww < 4; ww++) {
        float hv = wh[ww];
        Z += (hv > 0.0f) ? hv * expf(wm[ww] - M) : 0.0f;
    }

    float4 acc = make_float4(0, 0, 0, 0), sh = make_float4(0, 0, 0, 0);
#pragma unroll
    for (int ww = 0; ww < 4; ww++) {
        float sc = (wh[ww] > 0.0f) ? expf(wm[ww] - M) : 0.0f;
        float4 g = mG[ww][t];
        acc.x += g.x * sc; acc.y += g.y * sc; acc.z += g.z * sc; acc.w += g.w * sc;
        float4 s4 = mS[ww][t];
        sh.x += s4.x; sh.y += s4.y; sh.z += s4.z; sh.w += s4.w;
    }
    float4 cs = ((const float4*)g_csum)[t];
    float invZ = 1.0f / Z;
    float4 o;
    o.x = (acc.x + em * (cs.x - sh.x)) * invZ;
    o.y = (acc.y + em * (cs.y - sh.y)) * invZ;
    o.z = (acc.z + em * (cs.z - sh.z)) * invZ;
    o.w = (acc.w + em * (cs.w - sh.w)) * invZ;
    ((float4*)(Xp + (size_t)row * F))[t] = o;
}

// ---------------- 6. LayerNorm (dense rows, no gather) -----------------------
__global__ __launch_bounds__(128) void ln_kernel(const float* __restrict__ T,
                                                 const float* __restrict__ lng,
                                                 const float* __restrict__ lnb,
                                                 float* __restrict__ Xt) {
    __shared__ float red[128];
    int row = blockIdx.x, t = threadIdx.x;
    float4 x = ((const float4*)(T + (size_t)row * F))[t];

    red[t] = x.x + x.y + x.z + x.w;
    __syncthreads();
    for (int s = 64; s > 0; s >>= 1) {
        if (t < s) red[t] += red[t + s];
        __syncthreads();
    }
    float mu = red[0] * (1.0f / F);
    __syncthreads();
    float dx = x.x - mu, dy = x.y - mu, dz = x.z - mu, dw = x.w - mu;
    red[t] = dx * dx + dy * dy + dz * dz + dw * dw;
    __syncthreads();
    for (int s = 64; s > 0; s >>= 1) {
        if (t < s) red[t] += red[t + s];
        __syncthreads();
    }
    float inv = rsqrtf(red[0] * (1.0f / F) + 1e-5f);

    float4 g4 = *(const float4*)(lng + (t << 2));
    float4 b4 = *(const float4*)(lnb + (t << 2));
    float4 o;
    o.x = dx * inv * g4.x + b4.x;
    o.y = dy * inv * g4.y + b4.y;
    o.z = dz * inv * g4.z + b4.z;
    o.w = dw * inv * g4.w + b4.w;
    ((float4*)(Xt + (size_t)row * F))[t] = o;
}

// ---------------- 7. Y = Xt @ gcn2_W -----------------------------------------
__global__ __launch_bounds__(256) void ygemm(const float* __restrict__ Xt,
                                             const float* __restrict__ W2,
                                             float* __restrict__ Y) {
    __shared__ float w2t[NCLS * F];
    int t = threadIdx.x;
    for (int i = t; i < NCLS * F; i += 256) {
        int c = i / F, k = i - c * F;
        w2t[i] = W2[k * NCLS + c];
    }
    __syncthreads();
    int warp = t >> 5, lane = t & 31;
    int row = blockIdx.x * 8 + warp;
    float p[NCLS];
#pragma unroll
    for (int c = 0; c < NCLS; c++) p[c] = 0.0f;
    const float* xr = Xt + (size_t)row * F;
    for (int k = lane; k < F; k += 32) {
        float xv = xr[k];
#pragma unroll
        for (int c = 0; c < NCLS; c++) p[c] += xv * w2t[c * F + k];
    }
#pragma unroll
    for (int c = 0; c < NCLS; c++) {
#pragma unroll
        for (int o = 16; o > 0; o >>= 1) p[c] += __shfl_xor_sync(0xFFFFFFFFu, p[c], o);
    }
    if (lane == 0) {
#pragma unroll
        for (int c = 0; c < NCLS; c++) Y[row * NCLS + c] = p[c];
    }
}

// ---------------- 8. z = adj @ Y + b2, row softmax ---------------------------
__global__ __launch_bounds__(256) void z_softmax(const float* __restrict__ Y,
                                                 const float* __restrict__ b2,
                                                 float* __restrict__ out) {
    int t = threadIdx.x;
    int row = blockIdx.x * 32 + (t >> 3);
    int c = t & 7;
    int len = g_len[row];
    const int* cols = g_col + row * ELLW;
    float acc = b2[c];
    for (int e = 0; e < len; e++) acc += __ldg(Y + __ldg(cols + e) * NCLS + c);
    float m = acc;
#pragma unroll
    for (int o = 4; o > 0; o >>= 1) m = fmaxf(m, __shfl_xor_sync(0xFFFFFFFFu, m, o));
    float ez = expf(acc - m);
    float s = ez;
#pragma unroll
    for (int o = 4; o > 0; o >>= 1) s += __shfl_xor_sync(0xFFFFFFFFu, s, o);
    out[row * NCLS + c] = ez / s;
}

// ---------------- launcher ---------------------------------------------------
extern "C" void kernel_launch(void* const* d_in, const int* in_sizes, int n_in,
                              void* d_out, int out_size) {
    const float* adj    = (const float*)d_in[0];
    const float* x      = (const float*)d_in[1];
    const float* gcn1_W = (const float*)d_in[2];
    const float* gcn1_b = (const float*)d_in[3];
    const float* Qw     = (const float*)d_in[4];
    const float* Qb     = (const float*)d_in[5];
    const float* Kw     = (const float*)d_in[6];
    const float* Kb     = (const float*)d_in[7];
    const float* Vw     = (const float*)d_in[8];
    const float* Vb     = (const float*)d_in[9];
    const float* ln_g   = (const float*)d_in[10];
    const float* ln_b   = (const float*)d_in[11];
    const float* gcn2_W = (const float*)d_in[12];
    const float* gcn2_b = (const float*)d_in[13];
    float* out = (float*)d_out;

    float *XW, *H, *Rp, *T, *Xt, *Y, *M;
    cudaGetSymbolAddress((void**)&XW, g_XW);
    cudaGetSymbolAddress((void**)&H,  g_h);
    cudaGetSymbolAddress((void**)&Rp, g_R);
    cudaGetSymbolAddress((void**)&T,  g_V);
    cudaGetSymbolAddress((void**)&Xt, g_Xt);
    cudaGetSymbolAddress((void**)&Y,  g_Y);
    cudaGetSymbolAddress((void**)&M,  g_N);

    static cudaStream_t s1 = nullptr;
    static cudaEvent_t evFork = nullptr, evPrep = nullptr;
    if (!s1) {
        cudaStreamCreateWithFlags(&s1, cudaStreamNonBlocking);
        cudaEventCreateWithFlags(&evFork, cudaEventDisableTiming);
        cudaEventCreateWithFlags(&evPrep, cudaEventDisableTiming);
    }

    dim3 gg(F / 128, NROWS / 128);

    // fork: build_ell (HBM) on stream 0 ∥ GEMM-prep on s1
    cudaEventRecord(evFork, 0);
    cudaStreamWaitEvent(s1, evFork, 0);

    build_ell<<<NROWS / 4, 128, 0, 0>>>(adj);

    sgemm512<<<gg, 256, 0, s1>>>(x, gcn1_W, nullptr, XW);
    gemm_abt512<<<dim3(8, 8), 256, 0, s1>>>(Qw, Kw, M);   // M = Qw @ Kw^T
    uvc_kernel<<<129, 256, 0, s1>>>(Qw, Qb, Kw, Kb);
    cudaEventRecord(evPrep, s1);
    cudaStreamWaitEvent(0, evPrep, 0);

    // join: needs ELL + XW + u + v
    spmm_relu_bav<<<NROWS, 128, 0, 0>>>(XW, gcn1_b, H);

    sgemm512<<<gg, 256, 0, 0>>>(H, M, nullptr, Rp);       // R' = h @ M
    colsum_part<<<32, 512, 0, 0>>>(H);
    colsum_final<<<1, 512, 0, 0>>>();

    attn_fused<<<NROWS, 128, 0, 0>>>(H, Rp, XW);          // Xpre -> reuse g_XW

    sgemm512<<<gg, 256, 0, 0>>>(XW, Vw, Vb, T);           // T = Xpre@Vw + Vb
    ln_kernel<<<NROWS, 128, 0, 0>>>(T, ln_g, ln_b, Xt);

    ygemm<<<NROWS / 8, 256, 0, 0>>>(Xt, gcn2_W, Y);
    z_softmax<<<NROWS / 32, 256, 0, 0>>>(Y, gcn2_b, out);
}